// round 13
// baseline (speedup 1.0000x reference)
#include <cuda_runtime.h>
#include <cuda_bf16.h>
#include <cstdint>

#define NN 50000
#define EE 400000
#define GG 64
#define NB 49   // ceil(NN/1024)
#define H0 25088            // 196 tiles * 128
#define H0T 196
#define H1T 195

// ---------------- scratch (static device globals; no allocs) ----------------
__device__ float g_bufA[NN * 512];
__device__ float g_bufB[NN * 512];
__device__ float g_resid[NN * 64];
__device__ float g_pp[GG * 16 * 64];
__device__ float g_dis[NN];
__device__ int   g_deg[NN];
__device__ int   g_rowptr[NN + 1];
__device__ int   g_cursor[NN];
__device__ int   g_col[EE];
__device__ int   g_bsum[64];
__device__ __nv_bfloat16 g_ah[NN * 512];
__device__ __nv_bfloat16 g_al[NN * 512];
__device__ __nv_bfloat16 g_bh[NN * 512];
__device__ __nv_bfloat16 g_bl[NN * 512];
__device__ __nv_bfloat16 g_xh[NN * 128];
__device__ __nv_bfloat16 g_xl[NN * 128];
__device__ __nv_bfloat16 g_wh[262144];
__device__ __nv_bfloat16 g_wl[262144];

__device__ __forceinline__ float lrelu(float v) { return v >= 0.f ? v : 0.01f * v; }

// ---------------- CSR build ----------------
__global__ void zero_kernel() {
    int i = blockIdx.x * blockDim.x + threadIdx.x;
    if (i < NN) g_deg[i] = 0;
}

__global__ void count_deg_kernel(const int* __restrict__ dst) {
    int i = blockIdx.x * blockDim.x + threadIdx.x;
    if (i < EE) atomicAdd(&g_deg[dst[i]], 1);
}

__global__ void bsum_kernel() {
    __shared__ int ws[32];
    int tid = threadIdx.x;
    int i = blockIdx.x * 1024 + tid;
    int v = (i < NN) ? g_deg[i] : 0;
    if (i < NN) g_dis[i] = rsqrtf(1.f + (float)v);
    int s = v;
#pragma unroll
    for (int off = 16; off; off >>= 1) s += __shfl_xor_sync(0xFFFFFFFFu, s, off);
    if ((tid & 31) == 0) ws[tid >> 5] = s;
    __syncthreads();
    if (tid < 32) {
        int t = ws[tid];
#pragma unroll
        for (int off = 16; off; off >>= 1) t += __shfl_xor_sync(0xFFFFFFFFu, t, off);
        if (tid == 0) g_bsum[blockIdx.x] = t;
    }
}

__global__ void rowptr_kernel() {
    __shared__ int ws[32];
    __shared__ int sboff[2];
    int tid = threadIdx.x, lane = tid & 31, w = tid >> 5;
    if (w < 2) {
        int idx = w * 32 + lane;
        int bv = (idx < NB && idx < blockIdx.x) ? g_bsum[idx] : 0;
#pragma unroll
        for (int off = 16; off; off >>= 1) bv += __shfl_xor_sync(0xFFFFFFFFu, bv, off);
        if (lane == 0) sboff[w] = bv;
    }
    int i = blockIdx.x * 1024 + tid;
    if (i < NN) g_cursor[i] = 0;
    int v = (i < NN) ? g_deg[i] : 0;
    int x = v;
#pragma unroll
    for (int off = 1; off < 32; off <<= 1) {
        int t = __shfl_up_sync(0xFFFFFFFFu, x, off);
        if (lane >= off) x += t;
    }
    if (lane == 31) ws[w] = x;
    __syncthreads();
    if (tid < 32) {
        int y = ws[tid];
#pragma unroll
        for (int off = 1; off < 32; off <<= 1) {
            int t = __shfl_up_sync(0xFFFFFFFFu, y, off);
            if (tid >= off) y += t;
        }
        ws[tid] = y;
    }
    __syncthreads();
    int boff = sboff[0] + sboff[1];
    int incl = x + (w > 0 ? ws[w - 1] : 0) + boff;
    if (i < NN) g_rowptr[i + 1] = incl;
    if (i == 0) g_rowptr[0] = 0;
}

__global__ void fill_kernel(const int* __restrict__ src, const int* __restrict__ dst) {
    int i = blockIdx.x * blockDim.x + threadIdx.x;
    if (i < EE) {
        int d = dst[i];
        int pos = atomicAdd(&g_cursor[d], 1);
        g_col[g_rowptr[d] + pos] = src[i];
    }
}

// ---------------- fp32 -> bf16 hi/lo split ----------------
__global__ void split_kernel(const float4* __restrict__ in, uint2* __restrict__ hi,
                             uint2* __restrict__ lo, int count4) {
    int i = blockIdx.x * blockDim.x + threadIdx.x;
    if (i < count4) {
        float4 v = in[i];
        __nv_bfloat16 h0 = __float2bfloat16_rn(v.x);
        __nv_bfloat16 h1 = __float2bfloat16_rn(v.y);
        __nv_bfloat16 h2 = __float2bfloat16_rn(v.z);
        __nv_bfloat16 h3 = __float2bfloat16_rn(v.w);
        __nv_bfloat162 t;
        uint2 ph, pl;
        t.x = h0; t.y = h1; ph.x = *reinterpret_cast<uint32_t*>(&t);
        t.x = h2; t.y = h3; ph.y = *reinterpret_cast<uint32_t*>(&t);
        t.x = __float2bfloat16_rn(v.x - __bfloat162float(h0));
        t.y = __float2bfloat16_rn(v.y - __bfloat162float(h1));
        pl.x = *reinterpret_cast<uint32_t*>(&t);
        t.x = __float2bfloat16_rn(v.z - __bfloat162float(h2));
        t.y = __float2bfloat16_rn(v.w - __bfloat162float(h3));
        pl.y = *reinterpret_cast<uint32_t*>(&t);
        hi[i] = ph;
        lo[i] = pl;
    }
}

__global__ void wsplit_all_kernel(const float* __restrict__ W1, const float* __restrict__ Wr,
                                  const float* __restrict__ W2, const float* __restrict__ W3,
                                  const float* __restrict__ W4,
                                  __nv_bfloat16* __restrict__ th, __nv_bfloat16* __restrict__ tl) {
    int i = blockIdx.x * blockDim.x + threadIdx.x;
    if (i >= 196608) return;
    const float* W; int off, K, N, j;
    if (i < 8192)        { W = W1; off = 0;      K = 128; N = 64;  j = i; }
    else if (i < 16384)  { W = Wr; off = 8192;   K = 128; N = 64;  j = i - 8192; }
    else if (i < 32768)  { W = W2; off = 16384;  K = 64;  N = 256; j = i - 16384; }
    else if (i < 163840) { W = W3; off = 32768;  K = 256; N = 512; j = i - 32768; }
    else                 { W = W4; off = 163840; K = 512; N = 64;  j = i - 163840; }
    int k = j / N, n = j % N;
    float v = W[j];
    __nv_bfloat16 h = __float2bfloat16_rn(v);
    th[off + n * K + k] = h;
    tl[off + n * K + k] = __float2bfloat16_rn(v - __bfloat162float(h));
}

// ---------------- PTX helpers ----------------
__device__ __forceinline__ void mma_bf16(float* c, const uint32_t* a, const uint32_t* b) {
    asm volatile(
        "mma.sync.aligned.m16n8k16.row.col.f32.bf16.bf16.f32 "
        "{%0,%1,%2,%3}, {%4,%5,%6,%7}, {%8,%9}, {%0,%1,%2,%3};"
        : "+f"(c[0]), "+f"(c[1]), "+f"(c[2]), "+f"(c[3])
        : "r"(a[0]), "r"(a[1]), "r"(a[2]), "r"(a[3]), "r"(b[0]), "r"(b[1]));
}
__device__ __forceinline__ void ldsm4(uint32_t* r, uint32_t addr) {
    asm volatile("ldmatrix.sync.aligned.m8n8.x4.shared.b16 {%0,%1,%2,%3}, [%4];"
                 : "=r"(r[0]), "=r"(r[1]), "=r"(r[2]), "=r"(r[3]) : "r"(addr));
}
__device__ __forceinline__ void cp16(uint32_t saddr, const void* g, bool valid) {
    int sz = valid ? 16 : 0;
    asm volatile("cp.async.cg.shared.global [%0], [%1], 16, %2;\n"
                 :: "r"(saddr), "l"(g), "r"(sz));
}
__device__ __forceinline__ void cp_commit() {
    asm volatile("cp.async.commit_group;\n" ::: "memory");
}
template <int N>
__device__ __forceinline__ void cp_wait() {
    asm volatile("cp.async.wait_group %0;\n" :: "n"(N) : "memory");
}

// ---------------- 2-stage pipelined split-bf16 HMMA GEMM (2 CTAs/SM, BM=128) ----------------
// row0: first row handled by this launch (grid covers a row range).
template <int K, int NCOLS, bool BIAS, bool SPLIT_EPI, bool DUAL, bool ROW_SCALE>
__global__ __launch_bounds__(256, 2)
void mm_kernel(const __nv_bfloat16* __restrict__ Ah, const __nv_bfloat16* __restrict__ Al,
               const __nv_bfloat16* __restrict__ Bh, const __nv_bfloat16* __restrict__ Bl,
               const float* __restrict__ bias, float* __restrict__ C,
               __nv_bfloat16* __restrict__ Chi, __nv_bfloat16* __restrict__ Clo,
               float* __restrict__ C2, int row0, int M) {
    constexpr int BM = 128;
    constexpr int BN = (NCOLS < 128) ? NCOLS : 128;
    constexpr int BK = 32;
    constexpr int SA = BK + 8;
    constexpr int WM = (BN == 64) ? 32 : 64;
    constexpr int WN = 32;
    constexpr int WGN = BN / WN;
    constexpr int MFR = WM / 16;
    constexpr int NFR = WN / 8;
    constexpr int NT = K / BK;
    constexpr int STG = 2 * (BM + BN) * SA;

    extern __shared__ __nv_bfloat16 smem[];
    const uint32_t sbase = (uint32_t)__cvta_generic_to_shared(smem);

    const int tid = threadIdx.x, wid = tid >> 5, lane = tid & 31;
    const int warp_m = wid / WGN, warp_n = wid % WGN;
    const int rowBase = row0 + blockIdx.x * BM;
    const int colBase = blockIdx.y * BN;
    const int gID = lane >> 2, tig = lane & 3;

    float acc[MFR][NFR][4] = {};

    auto load_stage = [&](int k0, int st) {
        const int aoff = st * STG;
#pragma unroll
        for (int i = tid; i < BM * 4; i += 256) {
            int r = i >> 2, q = i & 3;
            int gr = rowBase + r;
            bool ok = gr < M;
            size_t go = (size_t)(ok ? gr : 0) * K + k0 + q * 8;
            uint32_t sa = sbase + (uint32_t)(aoff + r * SA + q * 8) * 2;
            cp16(sa, Ah + go, ok);
            cp16(sa + (uint32_t)(BM * SA) * 2, Al + go, ok);
        }
        const int boff = st * STG + 2 * BM * SA;
#pragma unroll
        for (int i = tid; i < BN * 4; i += 256) {
            int r = i >> 2, q = i & 3;
            size_t go = (size_t)(colBase + r) * K + k0 + q * 8;
            uint32_t sa = sbase + (uint32_t)(boff + r * SA + q * 8) * 2;
            cp16(sa, Bh + go, true);
            cp16(sa + (uint32_t)(BN * SA) * 2, Bl + go, true);
        }
        cp_commit();
    };

    load_stage(0, 0);
    if (NT > 1) load_stage(BK, 1);

    for (int kt = 0; kt < NT; kt++) {
        if (kt + 1 < NT) cp_wait<1>(); else cp_wait<0>();
        __syncthreads();

        const int st = kt & 1;
        const uint32_t ah_base = sbase + (uint32_t)(st * STG) * 2;
        const uint32_t al_base = ah_base + (uint32_t)(BM * SA) * 2;
        const uint32_t bh_base = ah_base + (uint32_t)(2 * BM * SA) * 2;
        const uint32_t bl_base = bh_base + (uint32_t)(BN * SA) * 2;

#pragma unroll
        for (int kk = 0; kk < BK; kk += 16) {
            uint32_t bfh[NFR][2], bfl[NFR][2];
            int bn = warp_n * WN + ((lane >> 4) << 3) + (lane & 7);
            int bk = kk + ((lane >> 3) & 1) * 8;
#pragma unroll
            for (int pr = 0; pr < NFR / 2; pr++) {
                uint32_t off = (uint32_t)((bn + pr * 16) * SA + bk) * 2;
                uint32_t rh[4], rl[4];
                ldsm4(rh, bh_base + off);
                ldsm4(rl, bl_base + off);
                bfh[pr * 2][0] = rh[0]; bfh[pr * 2][1] = rh[1];
                bfh[pr * 2 + 1][0] = rh[2]; bfh[pr * 2 + 1][1] = rh[3];
                bfl[pr * 2][0] = rl[0]; bfl[pr * 2][1] = rl[1];
                bfl[pr * 2 + 1][0] = rl[2]; bfl[pr * 2 + 1][1] = rl[3];
            }
            int arow = warp_m * WM + (lane & 15);
            int acol = kk + ((lane >> 4) << 3);
#pragma unroll
            for (int mf = 0; mf < MFR; mf++) {
                uint32_t afh[4], afl[4];
                uint32_t off = (uint32_t)((arow + mf * 16) * SA + acol) * 2;
                ldsm4(afh, ah_base + off);
                ldsm4(afl, al_base + off);
#pragma unroll
                for (int nf = 0; nf < NFR; nf++) {
                    mma_bf16(acc[mf][nf], afh, bfh[nf]);
                    mma_bf16(acc[mf][nf], afh, bfl[nf]);
                    mma_bf16(acc[mf][nf], afl, bfh[nf]);
                }
            }
        }
        if (kt + 2 < NT) {
            __syncthreads();
            load_stage((kt + 2) * BK, st);
        }
    }

    // ---- epilogue ----
#pragma unroll
    for (int mf = 0; mf < MFR; mf++) {
        int r0 = rowBase + warp_m * WM + mf * 16 + gID;
        float d0 = 1.f, d1 = 1.f;
        if (ROW_SCALE) {
            d0 = (r0 < M) ? g_dis[r0] : 0.f;
            d1 = (r0 + 8 < M) ? g_dis[r0 + 8] : 0.f;
        }
#pragma unroll
        for (int nf = 0; nf < NFR; nf++) {
            int col = colBase + warp_n * WN + nf * 8 + tig * 2;
            float v0 = acc[mf][nf][0], v1 = acc[mf][nf][1];
            float v2 = acc[mf][nf][2], v3 = acc[mf][nf][3];
            if (DUAL) {
                if (col < 64) {
                    if (r0 < M)
                        *reinterpret_cast<float2*>(C + (size_t)r0 * 64 + col) = make_float2(v0, v1);
                    if (r0 + 8 < M)
                        *reinterpret_cast<float2*>(C + (size_t)(r0 + 8) * 64 + col) = make_float2(v2, v3);
                } else {
                    int c2 = col - 64;
                    float bb0 = bias[c2], bb1 = bias[c2 + 1];
                    v0 += bb0; v1 += bb1; v2 += bb0; v3 += bb1;
                    if (r0 < M)
                        *reinterpret_cast<float2*>(C2 + (size_t)r0 * 64 + c2) = make_float2(v0, v1);
                    if (r0 + 8 < M)
                        *reinterpret_cast<float2*>(C2 + (size_t)(r0 + 8) * 64 + c2) = make_float2(v2, v3);
                }
                continue;
            }
            if (BIAS) {
                float bb0 = bias[col], bb1 = bias[col + 1];
                v0 += bb0; v1 += bb1; v2 += bb0; v3 += bb1;
            }
            if (ROW_SCALE) { v0 *= d0; v1 *= d0; v2 *= d1; v3 *= d1; }
            if (SPLIT_EPI) {
                v0 = lrelu(v0); v1 = lrelu(v1); v2 = lrelu(v2); v3 = lrelu(v3);
                if (r0 < M) {
                    __nv_bfloat16 h0 = __float2bfloat16_rn(v0);
                    __nv_bfloat16 h1 = __float2bfloat16_rn(v1);
                    __nv_bfloat162 ph, pl;
                    ph.x = h0; ph.y = h1;
                    pl.x = __float2bfloat16_rn(v0 - __bfloat162float(h0));
                    pl.y = __float2bfloat16_rn(v1 - __bfloat162float(h1));
                    *reinterpret_cast<__nv_bfloat162*>(Chi + (size_t)r0 * NCOLS + col) = ph;
                    *reinterpret_cast<__nv_bfloat162*>(Clo + (size_t)r0 * NCOLS + col) = pl;
                }
                if (r0 + 8 < M) {
                    __nv_bfloat16 h2 = __float2bfloat16_rn(v2);
                    __nv_bfloat16 h3 = __float2bfloat16_rn(v3);
                    __nv_bfloat162 ph, pl;
                    ph.x = h2; ph.y = h3;
                    pl.x = __float2bfloat16_rn(v2 - __bfloat162float(h2));
                    pl.y = __float2bfloat16_rn(v3 - __bfloat162float(h3));
                    *reinterpret_cast<__nv_bfloat162*>(Chi + (size_t)(r0 + 8) * NCOLS + col) = ph;
                    *reinterpret_cast<__nv_bfloat162*>(Clo + (size_t)(r0 + 8) * NCOLS + col) = pl;
                }
            } else {
                if (r0 < M)
                    *reinterpret_cast<float2*>(C + (size_t)r0 * NCOLS + col) = make_float2(v0, v1);
                if (r0 + 8 < M)
                    *reinterpret_cast<float2*>(C + (size_t)(r0 + 8) * NCOLS + col) = make_float2(v2, v3);
            }
        }
    }
}

// ---------------- CSR gather aggregation (node range [n0, n0+ncount)) ----------------
template <int F, bool LEAKY, bool BIAS, bool SPLIT, bool PRESCALED, bool OUTSCALE>
__global__ __launch_bounds__(256)
void agg_kernel(const float* __restrict__ in, float* __restrict__ out,
                const float* __restrict__ bias,
                __nv_bfloat16* __restrict__ oh, __nv_bfloat16* __restrict__ ol,
                int n0, int ncount) {
    int warp = (blockIdx.x * 256 + threadIdx.x) >> 5;
    int lane = threadIdx.x & 31;
    if (warp >= ncount) return;
    const int n = n0 + warp;
    const float dn = g_dis[n];
    constexpr int R = F / 32;
    float acc[R];
    const float wself = PRESCALED ? 1.f : dn * dn;
#pragma unroll
    for (int r = 0; r < R; r++) {
        float v = in[(size_t)n * F + lane + r * 32];
        if (LEAKY) v = lrelu(v);
        acc[r] = v * wself;
    }
    const int e0 = g_rowptr[n], e1 = g_rowptr[n + 1];
    int e = e0;
    for (; e + 3 < e1; e += 4) {
        int s0 = g_col[e], s1 = g_col[e + 1], s2 = g_col[e + 2], s3 = g_col[e + 3];
        float w0 = 1.f, w1 = 1.f, w2 = 1.f, w3 = 1.f;
        if (!PRESCALED) {
            w0 = g_dis[s0] * dn; w1 = g_dis[s1] * dn;
            w2 = g_dis[s2] * dn; w3 = g_dis[s3] * dn;
        }
#pragma unroll
        for (int r = 0; r < R; r++) {
            float va = in[(size_t)s0 * F + lane + r * 32];
            float vb = in[(size_t)s1 * F + lane + r * 32];
            float vc = in[(size_t)s2 * F + lane + r * 32];
            float vd = in[(size_t)s3 * F + lane + r * 32];
            if (LEAKY) { va = lrelu(va); vb = lrelu(vb); vc = lrelu(vc); vd = lrelu(vd); }
            if (PRESCALED) acc[r] += (va + vb) + (vc + vd);
            else acc[r] += va * w0 + vb * w1 + vc * w2 + vd * w3;
        }
    }
    for (; e < e1; e++) {
        int s0 = g_col[e];
        float w0 = PRESCALED ? 1.f : g_dis[s0] * dn;
#pragma unroll
        for (int r = 0; r < R; r++) {
            float va = in[(size_t)s0 * F + lane + r * 32];
            if (LEAKY) va = lrelu(va);
            acc[r] += PRESCALED ? va : va * w0;
        }
    }
#pragma unroll
    for (int r = 0; r < R; r++) {
        float o = acc[r];
        if (BIAS) o += bias[lane + r * 32];
        if (PRESCALED || OUTSCALE) o *= dn;
        if (SPLIT) {
            __nv_bfloat16 h = __float2bfloat16_rn(o);
            oh[(size_t)n * F + lane + r * 32] = h;
            ol[(size_t)n * F + lane + r * 32] = __float2bfloat16_rn(o - __bfloat162float(h));
        } else {
            out[(size_t)n * F + lane + r * 32] = o;
        }
    }
}

// ---------------- fused L4 agg (prescaled) + bias + leaky + residual + layernorm ----------------
__global__ __launch_bounds__(256)
void agg_ln_kernel(const float* __restrict__ q4, const float* __restrict__ b4,
                   const float* __restrict__ resid,
                   const float* __restrict__ gamma, const float* __restrict__ beta,
                   float* __restrict__ z) {
    int warp = (blockIdx.x * 256 + threadIdx.x) >> 5;
    int lane = threadIdx.x & 31;
    if (warp >= NN) return;
    const int n = warp;
    const float dn = g_dis[n];
    float a0 = q4[(size_t)n * 64 + lane];
    float a1 = q4[(size_t)n * 64 + lane + 32];
    const int e0 = g_rowptr[n], e1 = g_rowptr[n + 1];
    int e = e0;
    for (; e + 3 < e1; e += 4) {
        int s0 = g_col[e], s1 = g_col[e + 1], s2 = g_col[e + 2], s3 = g_col[e + 3];
        a0 += (q4[(size_t)s0 * 64 + lane] + q4[(size_t)s1 * 64 + lane])
            + (q4[(size_t)s2 * 64 + lane] + q4[(size_t)s3 * 64 + lane]);
        a1 += (q4[(size_t)s0 * 64 + lane + 32] + q4[(size_t)s1 * 64 + lane + 32])
            + (q4[(size_t)s2 * 64 + lane + 32] + q4[(size_t)s3 * 64 + lane + 32]);
    }
    for (; e < e1; e++) {
        int s0 = g_col[e];
        a0 += q4[(size_t)s0 * 64 + lane];
        a1 += q4[(size_t)s0 * 64 + lane + 32];
    }
    float v0 = lrelu(a0 * dn + b4[lane]) + resid[(size_t)n * 64 + lane];
    float v1 = lrelu(a1 * dn + b4[lane + 32]) + resid[(size_t)n * 64 + lane + 32];
    float s = v0 + v1, sq = v0 * v0 + v1 * v1;
#pragma unroll
    for (int off = 16; off; off >>= 1) {
        s += __shfl_xor_sync(0xFFFFFFFFu, s, off);
        sq += __shfl_xor_sync(0xFFFFFFFFu, sq, off);
    }
    float mean = s * (1.f / 64.f);
    float var = sq * (1.f / 64.f) - mean * mean;
    float inv = rsqrtf(var + 1e-5f);
    z[(size_t)n * 64 + lane]      = (v0 - mean) * inv * gamma[lane]      + beta[lane];
    z[(size_t)n * 64 + lane + 32] = (v1 - mean) * inv * gamma[lane + 32] + beta[lane + 32];
}

// ---------------- pool stage 1 ----------------
__global__ void pool1_kernel(const float* __restrict__ z) {
    int g = blockIdx.x, part = blockIdx.y, j = threadIdx.x;
    int s = (g * NN + GG - 1) / GG;
    int e = ((g + 1) * NN + GG - 1) / GG;
    int cnt = e - s;
    int ps = s + (cnt * part) / 16;
    int pe = s + (cnt * (part + 1)) / 16;
    float m = -3.402823e38f;
    for (int n = ps; n < pe; n++) m = fmaxf(m, z[(size_t)n * 64 + j]);
    g_pp[(g * 16 + part) * 64 + j] = m;
}

// ---------------- fused pool stage 2 + head ----------------
__global__ void head_kernel(const float* __restrict__ fc1W, const float* __restrict__ fc1b,
                            const float* __restrict__ fng, const float* __restrict__ fnb,
                            const float* __restrict__ fc2W, const float* __restrict__ fc2b,
                            float* __restrict__ out) {
    __shared__ float ps[64];
    __shared__ float q[64];
    __shared__ float red[64];
    int g = blockIdx.x, j = threadIdx.x;
    float m = -3.402823e38f;
#pragma unroll
    for (int part = 0; part < 16; part++)
        m = fmaxf(m, g_pp[(g * 16 + part) * 64 + j]);
    ps[j] = m;
    __syncthreads();
    float acc = fc1b[j];
#pragma unroll 8
    for (int k = 0; k < 64; k++) acc += ps[k] * fc1W[k * 64 + j];
    red[j] = acc;
    __syncthreads();
#pragma unroll
    for (int off = 32; off; off >>= 1) { if (j < off) red[j] += red[j + off]; __syncthreads(); }
    float mean = red[0] * (1.f / 64.f);
    __syncthreads();
    float d = acc - mean;
    red[j] = d * d;
    __syncthreads();
#pragma unroll
    for (int off = 32; off; off >>= 1) { if (j < off) red[j] += red[j + off]; __syncthreads(); }
    float var = red[0] * (1.f / 64.f);
    float qn = d * rsqrtf(var + 1e-5f) * fng[j] + fnb[j];
    q[j] = lrelu(qn);
    __syncthreads();
    if (j < 16) {
        float o = fc2b[j];
#pragma unroll 8
        for (int k = 0; k < 64; k++) o += q[k] * fc2W[k * 16 + j];
        out[g * 16 + j] = o;
    }
}

// ---------------- launcher ----------------
static inline int mm_smem_bytes(int bn) { return 2 * 2 * (128 + bn) * 40 * 2; }

extern "C" void kernel_launch(void* const* d_in, const int* in_sizes, int n_in,
                              void* d_out, int out_size) {
    (void)in_sizes; (void)n_in; (void)out_size;
    const float* x   = (const float*)d_in[0];
    const int*   ei  = (const int*)d_in[1];
    const float *W1 = (const float*)d_in[3],  *b1 = (const float*)d_in[4];
    const float *W2 = (const float*)d_in[5],  *b2 = (const float*)d_in[6];
    const float *W3 = (const float*)d_in[7],  *b3 = (const float*)d_in[8];
    const float *W4 = (const float*)d_in[9],  *b4 = (const float*)d_in[10];
    const float *Wr = (const float*)d_in[11], *br = (const float*)d_in[12];
    const float *lng = (const float*)d_in[13], *lnb = (const float*)d_in[14];
    const float *fc1W = (const float*)d_in[15], *fc1b = (const float*)d_in[16];
    const float *fng = (const float*)d_in[17], *fnb = (const float*)d_in[18];
    const float *fc2W = (const float*)d_in[19], *fc2b = (const float*)d_in[20];
    float* out = (float*)d_out;

    float *bufA, *bufB, *resid;
    __nv_bfloat16 *ah, *al, *bh, *bl, *xh, *xl, *wh, *wl;
    cudaGetSymbolAddress((void**)&bufA, g_bufA);
    cudaGetSymbolAddress((void**)&bufB, g_bufB);
    cudaGetSymbolAddress((void**)&resid, g_resid);
    cudaGetSymbolAddress((void**)&ah, g_ah);
    cudaGetSymbolAddress((void**)&al, g_al);
    cudaGetSymbolAddress((void**)&bh, g_bh);
    cudaGetSymbolAddress((void**)&bl, g_bl);
    cudaGetSymbolAddress((void**)&xh, g_xh);
    cudaGetSymbolAddress((void**)&xl, g_xl);
    cudaGetSymbolAddress((void**)&wh, g_wh);
    cudaGetSymbolAddress((void**)&wl, g_wl);

    __nv_bfloat16 *w1h = wh + 0,      *w1l = wl + 0;
    __nv_bfloat16 *w2h = wh + 16384,  *w2l = wl + 16384;
    __nv_bfloat16 *w3h = wh + 32768,  *w3l = wl + 32768;
    __nv_bfloat16 *w4h = wh + 163840, *w4l = wl + 163840;

    const int* src = ei;
    const int* dst = ei + EE;

    cudaFuncSetAttribute(mm_kernel<128, 128, false, false, true, false>, cudaFuncAttributeMaxDynamicSharedMemorySize, mm_smem_bytes(128));
    cudaFuncSetAttribute(mm_kernel<64, 256, true, false, false, true>,   cudaFuncAttributeMaxDynamicSharedMemorySize, mm_smem_bytes(128));
    cudaFuncSetAttribute(mm_kernel<256, 512, true, true, false, false>,  cudaFuncAttributeMaxDynamicSharedMemorySize, mm_smem_bytes(128));
    cudaFuncSetAttribute(mm_kernel<512, 64, false, false, false, true>,  cudaFuncAttributeMaxDynamicSharedMemorySize, mm_smem_bytes(64));

    static cudaStream_t s2 = nullptr;
    static cudaEvent_t ev[10] = {};
    if (s2 == nullptr) {
        cudaStreamCreateWithFlags(&s2, cudaStreamNonBlocking);
        for (int i = 0; i < 10; i++) cudaEventCreateWithFlags(&ev[i], cudaEventDisableTiming);
    }

    const int MT = (NN + 127) / 128;
    const int AGG_H0B = (H0 + 7) / 8;
    const int AGG_H1B = (NN - H0 + 7) / 8;
    const int AGG_FULL = (NN + 7) / 8;

    // ---- fork: CSR+wsplit on s2, x-split + mm1 on legacy ----
    cudaEventRecord(ev[0], 0);
    cudaStreamWaitEvent(s2, ev[0], 0);

    wsplit_all_kernel<<<(196608 + 255) / 256, 256, 0, s2>>>(W1, Wr, W2, W3, W4, wh, wl);
    cudaEventRecord(ev[1], s2);                       // weights ready
    zero_kernel<<<(NN + 255) / 256, 256, 0, s2>>>();
    count_deg_kernel<<<(EE + 255) / 256, 256, 0, s2>>>(dst);
    bsum_kernel<<<NB, 1024, 0, s2>>>();
    rowptr_kernel<<<NB, 1024, 0, s2>>>();
    fill_kernel<<<(EE + 255) / 256, 256, 0, s2>>>(src, dst);
    cudaEventRecord(ev[2], s2);                       // CSR ready

    split_kernel<<<(NN * 32 + 255) / 256, 256>>>(
        reinterpret_cast<const float4*>(x), reinterpret_cast<uint2*>(xh),
        reinterpret_cast<uint2*>(xl), NN * 32);
    cudaStreamWaitEvent(0, ev[1], 0);
    // mm1: t1 -> bufA, resid (DUAL)
    mm_kernel<128, 128, false, false, true, false><<<dim3(MT, 1), 256, mm_smem_bytes(128)>>>(
        xh, xl, w1h, w1l, br, bufA, nullptr, nullptr, resid, 0, NN);
    cudaStreamWaitEvent(0, ev[2], 0);                 // join CSR

    // agg1 (full, needs all t1): q1 -> bufB
    agg_kernel<64, false, true, false, false, true><<<AGG_FULL, 256>>>(bufA, bufB, b1, nullptr, nullptr, 0, NN);

    // ---- pipelined L2: agg2 halves (A) feed mm2 halves (B) ----
    // agg2: bufB(q1) -> ah/al
    agg_kernel<64, true, false, true, true, false><<<AGG_H0B, 256>>>(bufB, nullptr, nullptr, ah, al, 0, H0);
    cudaEventRecord(ev[3], 0);
    agg_kernel<64, true, false, true, true, false><<<AGG_H1B, 256>>>(bufB, nullptr, nullptr, ah, al, H0, NN - H0);
    cudaEventRecord(ev[4], 0);
    // mm2: ah/al -> bufA (q2), ROW_SCALE
    cudaStreamWaitEvent(s2, ev[3], 0);
    mm_kernel<64, 256, true, false, false, true><<<dim3(H0T, 2), 256, mm_smem_bytes(128), s2>>>(
        ah, al, w2h, w2l, b2, bufA, nullptr, nullptr, nullptr, 0, NN);
    cudaStreamWaitEvent(s2, ev[4], 0);
    mm_kernel<64, 256, true, false, false, true><<<dim3(H1T, 2), 256, mm_smem_bytes(128), s2>>>(
        ah, al, w2h, w2l, b2, bufA, nullptr, nullptr, nullptr, H0, NN);
    cudaEventRecord(ev[5], s2);                       // all q2 ready

    // ---- pipelined L3: agg3 halves (A) feed mm3 halves (B) ----
    cudaStreamWaitEvent(0, ev[5], 0);
    // agg3: bufA(q2) -> ah/al
    agg_kernel<256, true, false, true, true, false><<<AGG_H0B, 256>>>(bufA, nullptr, nullptr, ah, al, 0, H0);
    cudaEventRecord(ev[6], 0);
    agg_kernel<256, true, false, true, true, false><<<AGG_H1B, 256>>>(bufA, nullptr, nullptr, ah, al, H0, NN - H0);
    cudaEventRecord(ev[7], 0);
    // mm3: ah/al -> bh/bl (split epi)
    cudaStreamWaitEvent(s2, ev[6], 0);
    mm_kernel<256, 512, true, true, false, false><<<dim3(H0T, 4), 256, mm_smem_bytes(128), s2>>>(
        ah, al, w3h, w3l, b3, nullptr, bh, bl, nullptr, 0, NN);
    cudaEventRecord(ev[8], s2);
    cudaStreamWaitEvent(s2, ev[7], 0);
    mm_kernel<256, 512, true, true, false, false><<<dim3(H1T, 4), 256, mm_smem_bytes(128), s2>>>(
        ah, al, w3h, w3l, b3, nullptr, bh, bl, nullptr, H0, NN);
    cudaEventRecord(ev[9], s2);

    // ---- mm4 halves on A, overlapping mm3_h2 on B ----
    cudaStreamWaitEvent(0, ev[8], 0);
    mm_kernel<512, 64, false, false, false, true><<<dim3(H0T, 1), 256, mm_smem_bytes(64)>>>(
        bh, bl, w4h, w4l, nullptr, bufB, nullptr, nullptr, nullptr, 0, NN);
    cudaStreamWaitEvent(0, ev[9], 0);
    mm_kernel<512, 64, false, false, false, true><<<dim3(H1T, 1), 256, mm_smem_bytes(64)>>>(
        bh, bl, w4h, w4l, nullptr, bufB, nullptr, nullptr, nullptr, H0, NN);

    // agg_ln: bufB(q4)+resid -> bufA (z)
    agg_ln_kernel<<<AGG_FULL, 256>>>(bufB, b4, resid, lng, lnb, bufA);
    pool1_kernel<<<dim3(GG, 16), 64>>>(bufA);
    head_kernel<<<GG, 64>>>(fc1W, fc1b, fng, fnb, fc2W, fc2b, out);
}

// round 14
// speedup vs baseline: 1.0358x; 1.0358x over previous
#include <cuda_runtime.h>
#include <cuda_bf16.h>
#include <cstdint>

#define NN 50000
#define EE 400000
#define GG 64
#define NB 49   // ceil(NN/1024)

// ---------------- scratch (static device globals; no allocs) ----------------
__device__ float g_bufA[NN * 512];
__device__ float g_bufB[NN * 512];
__device__ float g_resid[NN * 64];
__device__ unsigned int g_poolu[GG * 64];
__device__ float g_dis[NN];
__device__ int   g_deg[NN];
__device__ int   g_rowptr[NN + 1];
__device__ int   g_cursor[NN];
__device__ int   g_col[EE];
__device__ int   g_bsum[64];
__device__ __nv_bfloat16 g_ah[NN * 512];
__device__ __nv_bfloat16 g_al[NN * 512];
__device__ __nv_bfloat16 g_bh[NN * 512];
__device__ __nv_bfloat16 g_bl[NN * 512];
__device__ __nv_bfloat16 g_xh[NN * 128];
__device__ __nv_bfloat16 g_xl[NN * 128];
__device__ __nv_bfloat16 g_wh[262144];
__device__ __nv_bfloat16 g_wl[262144];

__device__ __forceinline__ float lrelu(float v) { return v >= 0.f ? v : 0.01f * v; }

// order-preserving float <-> uint encoding (for atomicMax-as-fmax)
__device__ __forceinline__ unsigned int f2ou(float f) {
    unsigned int u = __float_as_uint(f);
    return (u & 0x80000000u) ? ~u : (u | 0x80000000u);
}
__device__ __forceinline__ float ou2f(unsigned int u) {
    return (u & 0x80000000u) ? __uint_as_float(u ^ 0x80000000u) : __uint_as_float(~u);
}

// ---------------- CSR build ----------------
__global__ void zero_kernel() {
    int i = blockIdx.x * blockDim.x + threadIdx.x;
    if (i < NN) g_deg[i] = 0;
    if (i < GG * 64) g_poolu[i] = 0u;   // encoded -inf
}

__global__ void count_deg_kernel(const int* __restrict__ dst) {
    int i = blockIdx.x * blockDim.x + threadIdx.x;
    if (i < EE) atomicAdd(&g_deg[dst[i]], 1);
}

__global__ void bsum_kernel() {
    __shared__ int ws[32];
    int tid = threadIdx.x;
    int i = blockIdx.x * 1024 + tid;
    int v = (i < NN) ? g_deg[i] : 0;
    if (i < NN) g_dis[i] = rsqrtf(1.f + (float)v);
    int s = v;
#pragma unroll
    for (int off = 16; off; off >>= 1) s += __shfl_xor_sync(0xFFFFFFFFu, s, off);
    if ((tid & 31) == 0) ws[tid >> 5] = s;
    __syncthreads();
    if (tid < 32) {
        int t = ws[tid];
#pragma unroll
        for (int off = 16; off; off >>= 1) t += __shfl_xor_sync(0xFFFFFFFFu, t, off);
        if (tid == 0) g_bsum[blockIdx.x] = t;
    }
}

// rowptr with inlined block-offset reduction + cursor zeroing
__global__ void rowptr_kernel() {
    __shared__ int ws[32];
    __shared__ int sboff[2];
    int tid = threadIdx.x, lane = tid & 31, w = tid >> 5;
    if (w < 2) {
        int idx = w * 32 + lane;
        int bv = (idx < NB && idx < blockIdx.x) ? g_bsum[idx] : 0;
#pragma unroll
        for (int off = 16; off; off >>= 1) bv += __shfl_xor_sync(0xFFFFFFFFu, bv, off);
        if (lane == 0) sboff[w] = bv;
    }
    int i = blockIdx.x * 1024 + tid;
    if (i < NN) g_cursor[i] = 0;
    int v = (i < NN) ? g_deg[i] : 0;
    int x = v;
#pragma unroll
    for (int off = 1; off < 32; off <<= 1) {
        int t = __shfl_up_sync(0xFFFFFFFFu, x, off);
        if (lane >= off) x += t;
    }
    if (lane == 31) ws[w] = x;
    __syncthreads();
    if (tid < 32) {
        int y = ws[tid];
#pragma unroll
        for (int off = 1; off < 32; off <<= 1) {
            int t = __shfl_up_sync(0xFFFFFFFFu, y, off);
            if (tid >= off) y += t;
        }
        ws[tid] = y;
    }
    __syncthreads();
    int boff = sboff[0] + sboff[1];
    int incl = x + (w > 0 ? ws[w - 1] : 0) + boff;
    if (i < NN) g_rowptr[i + 1] = incl;
    if (i == 0) g_rowptr[0] = 0;
}

__global__ void fill_kernel(const int* __restrict__ src, const int* __restrict__ dst) {
    int i = blockIdx.x * blockDim.x + threadIdx.x;
    if (i < EE) {
        int d = dst[i];
        int pos = atomicAdd(&g_cursor[d], 1);
        g_col[g_rowptr[d] + pos] = src[i];
    }
}

// ---------------- fp32 -> bf16 hi/lo split (vectorized) ----------------
__global__ void split_kernel(const float4* __restrict__ in, uint2* __restrict__ hi,
                             uint2* __restrict__ lo, int count4) {
    int i = blockIdx.x * blockDim.x + threadIdx.x;
    if (i < count4) {
        float4 v = in[i];
        __nv_bfloat16 h0 = __float2bfloat16_rn(v.x);
        __nv_bfloat16 h1 = __float2bfloat16_rn(v.y);
        __nv_bfloat16 h2 = __float2bfloat16_rn(v.z);
        __nv_bfloat16 h3 = __float2bfloat16_rn(v.w);
        __nv_bfloat162 t;
        uint2 ph, pl;
        t.x = h0; t.y = h1; ph.x = *reinterpret_cast<uint32_t*>(&t);
        t.x = h2; t.y = h3; ph.y = *reinterpret_cast<uint32_t*>(&t);
        t.x = __float2bfloat16_rn(v.x - __bfloat162float(h0));
        t.y = __float2bfloat16_rn(v.y - __bfloat162float(h1));
        pl.x = *reinterpret_cast<uint32_t*>(&t);
        t.x = __float2bfloat16_rn(v.z - __bfloat162float(h2));
        t.y = __float2bfloat16_rn(v.w - __bfloat162float(h3));
        pl.y = *reinterpret_cast<uint32_t*>(&t);
        hi[i] = ph;
        lo[i] = pl;
    }
}

__global__ void wsplit_all_kernel(const float* __restrict__ W1, const float* __restrict__ Wr,
                                  const float* __restrict__ W2, const float* __restrict__ W3,
                                  const float* __restrict__ W4,
                                  __nv_bfloat16* __restrict__ th, __nv_bfloat16* __restrict__ tl) {
    int i = blockIdx.x * blockDim.x + threadIdx.x;
    if (i >= 196608) return;
    const float* W; int off, K, N, j;
    if (i < 8192)        { W = W1; off = 0;      K = 128; N = 64;  j = i; }
    else if (i < 16384)  { W = Wr; off = 8192;   K = 128; N = 64;  j = i - 8192; }
    else if (i < 32768)  { W = W2; off = 16384;  K = 64;  N = 256; j = i - 16384; }
    else if (i < 163840) { W = W3; off = 32768;  K = 256; N = 512; j = i - 32768; }
    else                 { W = W4; off = 163840; K = 512; N = 64;  j = i - 163840; }
    int k = j / N, n = j % N;
    float v = W[j];
    __nv_bfloat16 h = __float2bfloat16_rn(v);
    th[off + n * K + k] = h;
    tl[off + n * K + k] = __float2bfloat16_rn(v - __bfloat162float(h));
}

// ---------------- PTX helpers ----------------
__device__ __forceinline__ void mma_bf16(float* c, const uint32_t* a, const uint32_t* b) {
    asm volatile(
        "mma.sync.aligned.m16n8k16.row.col.f32.bf16.bf16.f32 "
        "{%0,%1,%2,%3}, {%4,%5,%6,%7}, {%8,%9}, {%0,%1,%2,%3};"
        : "+f"(c[0]), "+f"(c[1]), "+f"(c[2]), "+f"(c[3])
        : "r"(a[0]), "r"(a[1]), "r"(a[2]), "r"(a[3]), "r"(b[0]), "r"(b[1]));
}
__device__ __forceinline__ void ldsm4(uint32_t* r, uint32_t addr) {
    asm volatile("ldmatrix.sync.aligned.m8n8.x4.shared.b16 {%0,%1,%2,%3}, [%4];"
                 : "=r"(r[0]), "=r"(r[1]), "=r"(r[2]), "=r"(r[3]) : "r"(addr));
}
__device__ __forceinline__ void cp16(uint32_t saddr, const void* g, bool valid) {
    int sz = valid ? 16 : 0;
    asm volatile("cp.async.cg.shared.global [%0], [%1], 16, %2;\n"
                 :: "r"(saddr), "l"(g), "r"(sz));
}
__device__ __forceinline__ void cp_commit() {
    asm volatile("cp.async.commit_group;\n" ::: "memory");
}
template <int N>
__device__ __forceinline__ void cp_wait() {
    asm volatile("cp.async.wait_group %0;\n" :: "n"(N) : "memory");
}

// ---------------- 2-stage pipelined split-bf16 HMMA GEMM (2 CTAs/SM, BM=128) ----------------
template <int K, int NCOLS, bool BIAS, bool SPLIT_EPI, bool DUAL, bool ROW_SCALE>
__global__ __launch_bounds__(256, 2)
void mm_kernel(const __nv_bfloat16* __restrict__ Ah, const __nv_bfloat16* __restrict__ Al,
               const __nv_bfloat16* __restrict__ Bh, const __nv_bfloat16* __restrict__ Bl,
               const float* __restrict__ bias, float* __restrict__ C,
               __nv_bfloat16* __restrict__ Chi, __nv_bfloat16* __restrict__ Clo,
               float* __restrict__ C2, int M) {
    constexpr int BM = 128;
    constexpr int BN = (NCOLS < 128) ? NCOLS : 128;
    constexpr int BK = 32;
    constexpr int SA = BK + 8;
    constexpr int WM = (BN == 64) ? 32 : 64;
    constexpr int WN = 32;
    constexpr int WGN = BN / WN;
    constexpr int MFR = WM / 16;
    constexpr int NFR = WN / 8;
    constexpr int NT = K / BK;
    constexpr int STG = 2 * (BM + BN) * SA;

    extern __shared__ __nv_bfloat16 smem[];
    const uint32_t sbase = (uint32_t)__cvta_generic_to_shared(smem);

    const int tid = threadIdx.x, wid = tid >> 5, lane = tid & 31;
    const int warp_m = wid / WGN, warp_n = wid % WGN;
    const int rowBase = blockIdx.x * BM;
    const int colBase = blockIdx.y * BN;
    const int gID = lane >> 2, tig = lane & 3;

    float acc[MFR][NFR][4] = {};

    auto load_stage = [&](int k0, int st) {
        const int aoff = st * STG;
#pragma unroll
        for (int i = tid; i < BM * 4; i += 256) {
            int r = i >> 2, q = i & 3;
            int gr = rowBase + r;
            bool ok = gr < M;
            size_t go = (size_t)(ok ? gr : 0) * K + k0 + q * 8;
            uint32_t sa = sbase + (uint32_t)(aoff + r * SA + q * 8) * 2;
            cp16(sa, Ah + go, ok);
            cp16(sa + (uint32_t)(BM * SA) * 2, Al + go, ok);
        }
        const int boff = st * STG + 2 * BM * SA;
#pragma unroll
        for (int i = tid; i < BN * 4; i += 256) {
            int r = i >> 2, q = i & 3;
            size_t go = (size_t)(colBase + r) * K + k0 + q * 8;
            uint32_t sa = sbase + (uint32_t)(boff + r * SA + q * 8) * 2;
            cp16(sa, Bh + go, true);
            cp16(sa + (uint32_t)(BN * SA) * 2, Bl + go, true);
        }
        cp_commit();
    };

    load_stage(0, 0);
    if (NT > 1) load_stage(BK, 1);

    for (int kt = 0; kt < NT; kt++) {
        if (kt + 1 < NT) cp_wait<1>(); else cp_wait<0>();
        __syncthreads();

        const int st = kt & 1;
        const uint32_t ah_base = sbase + (uint32_t)(st * STG) * 2;
        const uint32_t al_base = ah_base + (uint32_t)(BM * SA) * 2;
        const uint32_t bh_base = ah_base + (uint32_t)(2 * BM * SA) * 2;
        const uint32_t bl_base = bh_base + (uint32_t)(BN * SA) * 2;

#pragma unroll
        for (int kk = 0; kk < BK; kk += 16) {
            uint32_t bfh[NFR][2], bfl[NFR][2];
            int bn = warp_n * WN + ((lane >> 4) << 3) + (lane & 7);
            int bk = kk + ((lane >> 3) & 1) * 8;
#pragma unroll
            for (int pr = 0; pr < NFR / 2; pr++) {
                uint32_t off = (uint32_t)((bn + pr * 16) * SA + bk) * 2;
                uint32_t rh[4], rl[4];
                ldsm4(rh, bh_base + off);
                ldsm4(rl, bl_base + off);
                bfh[pr * 2][0] = rh[0]; bfh[pr * 2][1] = rh[1];
                bfh[pr * 2 + 1][0] = rh[2]; bfh[pr * 2 + 1][1] = rh[3];
                bfl[pr * 2][0] = rl[0]; bfl[pr * 2][1] = rl[1];
                bfl[pr * 2 + 1][0] = rl[2]; bfl[pr * 2 + 1][1] = rl[3];
            }
            int arow = warp_m * WM + (lane & 15);
            int acol = kk + ((lane >> 4) << 3);
#pragma unroll
            for (int mf = 0; mf < MFR; mf++) {
                uint32_t afh[4], afl[4];
                uint32_t off = (uint32_t)((arow + mf * 16) * SA + acol) * 2;
                ldsm4(afh, ah_base + off);
                ldsm4(afl, al_base + off);
#pragma unroll
                for (int nf = 0; nf < NFR; nf++) {
                    mma_bf16(acc[mf][nf], afh, bfh[nf]);
                    mma_bf16(acc[mf][nf], afh, bfl[nf]);
                    mma_bf16(acc[mf][nf], afl, bfh[nf]);
                }
            }
        }
        if (kt + 2 < NT) {
            __syncthreads();
            load_stage((kt + 2) * BK, st);
        }
    }

    // ---- epilogue ----
#pragma unroll
    for (int mf = 0; mf < MFR; mf++) {
        int r0 = rowBase + warp_m * WM + mf * 16 + gID;
        float d0 = 1.f, d1 = 1.f;
        if (ROW_SCALE) {
            d0 = (r0 < M) ? g_dis[r0] : 0.f;
            d1 = (r0 + 8 < M) ? g_dis[r0 + 8] : 0.f;
        }
#pragma unroll
        for (int nf = 0; nf < NFR; nf++) {
            int col = colBase + warp_n * WN + nf * 8 + tig * 2;
            float v0 = acc[mf][nf][0], v1 = acc[mf][nf][1];
            float v2 = acc[mf][nf][2], v3 = acc[mf][nf][3];
            if (DUAL) {
                if (col < 64) {
                    if (r0 < M)
                        *reinterpret_cast<float2*>(C + (size_t)r0 * 64 + col) = make_float2(v0, v1);
                    if (r0 + 8 < M)
                        *reinterpret_cast<float2*>(C + (size_t)(r0 + 8) * 64 + col) = make_float2(v2, v3);
                } else {
                    int c2 = col - 64;
                    float bb0 = bias[c2], bb1 = bias[c2 + 1];
                    v0 += bb0; v1 += bb1; v2 += bb0; v3 += bb1;
                    if (r0 < M)
                        *reinterpret_cast<float2*>(C2 + (size_t)r0 * 64 + c2) = make_float2(v0, v1);
                    if (r0 + 8 < M)
                        *reinterpret_cast<float2*>(C2 + (size_t)(r0 + 8) * 64 + c2) = make_float2(v2, v3);
                }
                continue;
            }
            if (BIAS) {
                float bb0 = bias[col], bb1 = bias[col + 1];
                v0 += bb0; v1 += bb1; v2 += bb0; v3 += bb1;
            }
            if (ROW_SCALE) { v0 *= d0; v1 *= d0; v2 *= d1; v3 *= d1; }
            if (SPLIT_EPI) {
                v0 = lrelu(v0); v1 = lrelu(v1); v2 = lrelu(v2); v3 = lrelu(v3);
                if (r0 < M) {
                    __nv_bfloat16 h0 = __float2bfloat16_rn(v0);
                    __nv_bfloat16 h1 = __float2bfloat16_rn(v1);
                    __nv_bfloat162 ph, pl;
                    ph.x = h0; ph.y = h1;
                    pl.x = __float2bfloat16_rn(v0 - __bfloat162float(h0));
                    pl.y = __float2bfloat16_rn(v1 - __bfloat162float(h1));
                    *reinterpret_cast<__nv_bfloat162*>(Chi + (size_t)r0 * NCOLS + col) = ph;
                    *reinterpret_cast<__nv_bfloat162*>(Clo + (size_t)r0 * NCOLS + col) = pl;
                }
                if (r0 + 8 < M) {
                    __nv_bfloat16 h2 = __float2bfloat16_rn(v2);
                    __nv_bfloat16 h3 = __float2bfloat16_rn(v3);
                    __nv_bfloat162 ph, pl;
                    ph.x = h2; ph.y = h3;
                    pl.x = __float2bfloat16_rn(v2 - __bfloat162float(h2));
                    pl.y = __float2bfloat16_rn(v3 - __bfloat162float(h3));
                    *reinterpret_cast<__nv_bfloat162*>(Chi + (size_t)(r0 + 8) * NCOLS + col) = ph;
                    *reinterpret_cast<__nv_bfloat162*>(Clo + (size_t)(r0 + 8) * NCOLS + col) = pl;
                }
            } else {
                if (r0 < M)
                    *reinterpret_cast<float2*>(C + (size_t)r0 * NCOLS + col) = make_float2(v0, v1);
                if (r0 + 8 < M)
                    *reinterpret_cast<float2*>(C + (size_t)(r0 + 8) * NCOLS + col) = make_float2(v2, v3);
            }
        }
    }
}

// ---------------- CSR gather aggregation ----------------
template <int F, bool LEAKY, bool BIAS, bool SPLIT, bool PRESCALED, bool OUTSCALE>
__global__ __launch_bounds__(256)
void agg_kernel(const float* __restrict__ in, float* __restrict__ out,
                const float* __restrict__ bias,
                __nv_bfloat16* __restrict__ oh, __nv_bfloat16* __restrict__ ol) {
    int warp = (blockIdx.x * 256 + threadIdx.x) >> 5;
    int lane = threadIdx.x & 31;
    if (warp >= NN) return;
    const int n = warp;
    const float dn = g_dis[n];
    constexpr int R = F / 32;
    float acc[R];
    const float wself = PRESCALED ? 1.f : dn * dn;
#pragma unroll
    for (int r = 0; r < R; r++) {
        float v = in[(size_t)n * F + lane + r * 32];
        if (LEAKY) v = lrelu(v);
        acc[r] = v * wself;
    }
    const int e0 = g_rowptr[n], e1 = g_rowptr[n + 1];
    int e = e0;
    for (; e + 3 < e1; e += 4) {
        int s0 = g_col[e], s1 = g_col[e + 1], s2 = g_col[e + 2], s3 = g_col[e + 3];
        float w0 = 1.f, w1 = 1.f, w2 = 1.f, w3 = 1.f;
        if (!PRESCALED) {
            w0 = g_dis[s0] * dn; w1 = g_dis[s1] * dn;
            w2 = g_dis[s2] * dn; w3 = g_dis[s3] * dn;
        }
#pragma unroll
        for (int r = 0; r < R; r++) {
            float va = in[(size_t)s0 * F + lane + r * 32];
            float vb = in[(size_t)s1 * F + lane + r * 32];
            float vc = in[(size_t)s2 * F + lane + r * 32];
            float vd = in[(size_t)s3 * F + lane + r * 32];
            if (LEAKY) { va = lrelu(va); vb = lrelu(vb); vc = lrelu(vc); vd = lrelu(vd); }
            if (PRESCALED) acc[r] += (va + vb) + (vc + vd);
            else acc[r] += va * w0 + vb * w1 + vc * w2 + vd * w3;
        }
    }
    for (; e < e1; e++) {
        int s0 = g_col[e];
        float w0 = PRESCALED ? 1.f : g_dis[s0] * dn;
#pragma unroll
        for (int r = 0; r < R; r++) {
            float va = in[(size_t)s0 * F + lane + r * 32];
            if (LEAKY) va = lrelu(va);
            acc[r] += PRESCALED ? va : va * w0;
        }
    }
#pragma unroll
    for (int r = 0; r < R; r++) {
        float o = acc[r];
        if (BIAS) o += bias[lane + r * 32];
        if (PRESCALED || OUTSCALE) o *= dn;
        if (SPLIT) {
            __nv_bfloat16 h = __float2bfloat16_rn(o);
            oh[(size_t)n * F + lane + r * 32] = h;
            ol[(size_t)n * F + lane + r * 32] = __float2bfloat16_rn(o - __bfloat162float(h));
        } else {
            out[(size_t)n * F + lane + r * 32] = o;
        }
    }
}

// ---------------- fused L4 agg + bias + leaky + residual + LN + atomic max-pool ----------------
__global__ __launch_bounds__(256)
void agg_ln_pool_kernel(const float* __restrict__ q4, const float* __restrict__ b4,
                        const float* __restrict__ resid,
                        const float* __restrict__ gamma, const float* __restrict__ beta) {
    int warp = (blockIdx.x * 256 + threadIdx.x) >> 5;
    int lane = threadIdx.x & 31;
    if (warp >= NN) return;
    const int n = warp;
    const float dn = g_dis[n];
    float a0 = q4[(size_t)n * 64 + lane];
    float a1 = q4[(size_t)n * 64 + lane + 32];
    const int e0 = g_rowptr[n], e1 = g_rowptr[n + 1];
    int e = e0;
    for (; e + 3 < e1; e += 4) {
        int s0 = g_col[e], s1 = g_col[e + 1], s2 = g_col[e + 2], s3 = g_col[e + 3];
        a0 += (q4[(size_t)s0 * 64 + lane] + q4[(size_t)s1 * 64 + lane])
            + (q4[(size_t)s2 * 64 + lane] + q4[(size_t)s3 * 64 + lane]);
        a1 += (q4[(size_t)s0 * 64 + lane + 32] + q4[(size_t)s1 * 64 + lane + 32])
            + (q4[(size_t)s2 * 64 + lane + 32] + q4[(size_t)s3 * 64 + lane + 32]);
    }
    for (; e < e1; e++) {
        int s0 = g_col[e];
        a0 += q4[(size_t)s0 * 64 + lane];
        a1 += q4[(size_t)s0 * 64 + lane + 32];
    }
    float v0 = lrelu(a0 * dn + b4[lane]) + resid[(size_t)n * 64 + lane];
    float v1 = lrelu(a1 * dn + b4[lane + 32]) + resid[(size_t)n * 64 + lane + 32];
    float s = v0 + v1, sq = v0 * v0 + v1 * v1;
#pragma unroll
    for (int off = 16; off; off >>= 1) {
        s += __shfl_xor_sync(0xFFFFFFFFu, s, off);
        sq += __shfl_xor_sync(0xFFFFFFFFu, sq, off);
    }
    float mean = s * (1.f / 64.f);
    float var = sq * (1.f / 64.f) - mean * mean;
    float inv = rsqrtf(var + 1e-5f);
    float z0 = (v0 - mean) * inv * gamma[lane] + beta[lane];
    float z1 = (v1 - mean) * inv * gamma[lane + 32] + beta[lane + 32];
    // per-graph max pool via ordered-uint atomicMax (batch[n] = n*GG/NN, sorted)
    int g = (int)(((long long)n * GG) / NN);
    atomicMax(&g_poolu[g * 64 + lane], f2ou(z0));
    atomicMax(&g_poolu[g * 64 + lane + 32], f2ou(z1));
}

// ---------------- head (reads pooled encoded maxima) ----------------
__global__ void head_kernel(const float* __restrict__ fc1W, const float* __restrict__ fc1b,
                            const float* __restrict__ fng, const float* __restrict__ fnb,
                            const float* __restrict__ fc2W, const float* __restrict__ fc2b,
                            float* __restrict__ out) {
    __shared__ float ps[64];
    __shared__ float q[64];
    __shared__ float red[64];
    int g = blockIdx.x, j = threadIdx.x;
    ps[j] = ou2f(g_poolu[g * 64 + j]);
    __syncthreads();
    float acc = fc1b[j];
#pragma unroll 8
    for (int k = 0; k < 64; k++) acc += ps[k] * fc1W[k * 64 + j];
    red[j] = acc;
    __syncthreads();
#pragma unroll
    for (int off = 32; off; off >>= 1) { if (j < off) red[j] += red[j + off]; __syncthreads(); }
    float mean = red[0] * (1.f / 64.f);
    __syncthreads();
    float d = acc - mean;
    red[j] = d * d;
    __syncthreads();
#pragma unroll
    for (int off = 32; off; off >>= 1) { if (j < off) red[j] += red[j + off]; __syncthreads(); }
    float var = red[0] * (1.f / 64.f);
    float qn = d * rsqrtf(var + 1e-5f) * fng[j] + fnb[j];
    q[j] = lrelu(qn);
    __syncthreads();
    if (j < 16) {
        float o = fc2b[j];
#pragma unroll 8
        for (int k = 0; k < 64; k++) o += q[k] * fc2W[k * 16 + j];
        out[g * 16 + j] = o;
    }
}

// ---------------- launcher ----------------
static inline int mm_smem_bytes(int bn) { return 2 * 2 * (128 + bn) * 40 * 2; }

extern "C" void kernel_launch(void* const* d_in, const int* in_sizes, int n_in,
                              void* d_out, int out_size) {
    (void)in_sizes; (void)n_in; (void)out_size;
    const float* x   = (const float*)d_in[0];
    const int*   ei  = (const int*)d_in[1];
    const float *W1 = (const float*)d_in[3],  *b1 = (const float*)d_in[4];
    const float *W2 = (const float*)d_in[5],  *b2 = (const float*)d_in[6];
    const float *W3 = (const float*)d_in[7],  *b3 = (const float*)d_in[8];
    const float *W4 = (const float*)d_in[9],  *b4 = (const float*)d_in[10];
    const float *Wr = (const float*)d_in[11], *br = (const float*)d_in[12];
    const float *lng = (const float*)d_in[13], *lnb = (const float*)d_in[14];
    const float *fc1W = (const float*)d_in[15], *fc1b = (const float*)d_in[16];
    const float *fng = (const float*)d_in[17], *fnb = (const float*)d_in[18];
    const float *fc2W = (const float*)d_in[19], *fc2b = (const float*)d_in[20];
    float* out = (float*)d_out;

    float *bufA, *bufB, *resid;
    __nv_bfloat16 *ah, *al, *bh, *bl, *xh, *xl, *wh, *wl;
    cudaGetSymbolAddress((void**)&bufA, g_bufA);
    cudaGetSymbolAddress((void**)&bufB, g_bufB);
    cudaGetSymbolAddress((void**)&resid, g_resid);
    cudaGetSymbolAddress((void**)&ah, g_ah);
    cudaGetSymbolAddress((void**)&al, g_al);
    cudaGetSymbolAddress((void**)&bh, g_bh);
    cudaGetSymbolAddress((void**)&bl, g_bl);
    cudaGetSymbolAddress((void**)&xh, g_xh);
    cudaGetSymbolAddress((void**)&xl, g_xl);
    cudaGetSymbolAddress((void**)&wh, g_wh);
    cudaGetSymbolAddress((void**)&wl, g_wl);

    __nv_bfloat16 *w1h = wh + 0,      *w1l = wl + 0;
    __nv_bfloat16 *w2h = wh + 16384,  *w2l = wl + 16384;
    __nv_bfloat16 *w3h = wh + 32768,  *w3l = wl + 32768;
    __nv_bfloat16 *w4h = wh + 163840, *w4l = wl + 163840;

    const int* src = ei;
    const int* dst = ei + EE;

    cudaFuncSetAttribute(mm_kernel<128, 128, false, false, true, false>, cudaFuncAttributeMaxDynamicSharedMemorySize, mm_smem_bytes(128));
    cudaFuncSetAttribute(mm_kernel<64, 256, true, false, false, true>,   cudaFuncAttributeMaxDynamicSharedMemorySize, mm_smem_bytes(128));
    cudaFuncSetAttribute(mm_kernel<256, 512, true, true, false, false>,  cudaFuncAttributeMaxDynamicSharedMemorySize, mm_smem_bytes(128));
    cudaFuncSetAttribute(mm_kernel<512, 64, false, false, false, true>,  cudaFuncAttributeMaxDynamicSharedMemorySize, mm_smem_bytes(64));

    static cudaStream_t s2 = nullptr;
    static cudaEvent_t evFork = nullptr, evJoin = nullptr, evW = nullptr;
    if (s2 == nullptr) {
        cudaStreamCreateWithFlags(&s2, cudaStreamNonBlocking);
        cudaEventCreateWithFlags(&evFork, cudaEventDisableTiming);
        cudaEventCreateWithFlags(&evJoin, cudaEventDisableTiming);
        cudaEventCreateWithFlags(&evW, cudaEventDisableTiming);
    }

    const int MT = (NN + 127) / 128;
    const int AGG_BLOCKS = (NN + 7) / 8;

    // ---- fork ----
    cudaEventRecord(evFork, 0);
    cudaStreamWaitEvent(s2, evFork, 0);

    // s2 branch: weight split (gates mm_L1), then CSR chain
    wsplit_all_kernel<<<(196608 + 255) / 256, 256, 0, s2>>>(W1, Wr, W2, W3, W4, wh, wl);
    cudaEventRecord(evW, s2);
    zero_kernel<<<(NN + 255) / 256, 256, 0, s2>>>();
    count_deg_kernel<<<(EE + 255) / 256, 256, 0, s2>>>(dst);
    bsum_kernel<<<NB, 1024, 0, s2>>>();
    rowptr_kernel<<<NB, 1024, 0, s2>>>();
    fill_kernel<<<(EE + 255) / 256, 256, 0, s2>>>(src, dst);
    cudaEventRecord(evJoin, s2);

    // legacy branch: x split, then (after weights) L1 GEMM
    split_kernel<<<(NN * 32 + 255) / 256, 256>>>(
        reinterpret_cast<const float4*>(x), reinterpret_cast<uint2*>(xh),
        reinterpret_cast<uint2*>(xl), NN * 32);
    cudaStreamWaitEvent(0, evW, 0);
    mm_kernel<128, 128, false, false, true, false><<<dim3(MT, 1), 256, mm_smem_bytes(128)>>>(
        xh, xl, w1h, w1l, br, bufA, nullptr, nullptr, resid, NN);

    // ---- join ----
    cudaStreamWaitEvent(0, evJoin, 0);

    // agg1: q1 = dis[n]*(agg(t1)+b1)
    agg_kernel<64, false, true, false, false, true><<<AGG_BLOCKS, 256>>>(bufA, bufB, b1, nullptr, nullptr);
    // agg2 (prescaled): g2 -> split
    agg_kernel<64, true, false, true, true, false><<<AGG_BLOCKS, 256>>>(bufB, nullptr, nullptr, ah, al);
    // L2 GEMM with ROW_SCALE
    mm_kernel<64, 256, true, false, false, true><<<dim3(MT, 2), 256, mm_smem_bytes(128)>>>(
        ah, al, w2h, w2l, b2, bufB, nullptr, nullptr, nullptr, NN);
    // agg3 (prescaled): g3 -> split
    agg_kernel<256, true, false, true, true, false><<<AGG_BLOCKS, 256>>>(bufB, nullptr, nullptr, ah, al);
    // L3 GEMM (split epilogue)
    mm_kernel<256, 512, true, true, false, false><<<dim3(MT, 4), 256, mm_smem_bytes(128)>>>(
        ah, al, w3h, w3l, b3, nullptr, bh, bl, nullptr, NN);
    // L4 GEMM with ROW_SCALE
    mm_kernel<512, 64, false, false, false, true><<<dim3(MT, 1), 256, mm_smem_bytes(64)>>>(
        bh, bl, w4h, w4l, nullptr, bufA, nullptr, nullptr, nullptr, NN);
    // fused agg + LN + atomic max-pool (no z writeback)
    agg_ln_pool_kernel<<<AGG_BLOCKS, 256>>>(bufA, b4, resid, lng, lnb);
    // head reads pooled maxima directly
    head_kernel<<<GG, 64>>>(fc1W, fc1b, fng, fnb, fc2W, fc2b, out);
}

// round 15
// speedup vs baseline: 1.0777x; 1.0405x over previous
#include <cuda_runtime.h>
#include <cuda_bf16.h>
#include <cstdint>

#define NN 50000
#define EE 400000
#define GG 64
#define NB 49   // ceil(NN/1024)

// ---------------- scratch (static device globals; no allocs) ----------------
__device__ float g_bufA[NN * 512];
__device__ float g_bufB[NN * 512];
__device__ float g_resid[NN * 64];
__device__ float g_pp[GG * 16 * 64];
__device__ float g_dis[NN];
__device__ int   g_deg[NN];
__device__ int   g_rowptr[NN + 1];
__device__ int   g_cursor[NN];
__device__ int   g_col[EE];
__device__ int   g_bsum[64];
__device__ __nv_bfloat16 g_ah[NN * 512];
__device__ __nv_bfloat16 g_al[NN * 512];
__device__ __nv_bfloat16 g_bh[NN * 512];
__device__ __nv_bfloat16 g_bl[NN * 512];
__device__ __nv_bfloat16 g_xh[NN * 128];
__device__ __nv_bfloat16 g_xl[NN * 128];
__device__ __nv_bfloat16 g_wh[262144];
__device__ __nv_bfloat16 g_wl[262144];

__device__ __forceinline__ float lrelu(float v) { return v >= 0.f ? v : 0.01f * v; }

// ---------------- CSR build ----------------
__global__ void zero_kernel() {
    int i = blockIdx.x * blockDim.x + threadIdx.x;
    if (i < NN) g_deg[i] = 0;
}

__global__ void count_deg_kernel(const int* __restrict__ dst) {
    int i = blockIdx.x * blockDim.x + threadIdx.x;
    if (i < EE) atomicAdd(&g_deg[dst[i]], 1);
}

__global__ void bsum_kernel() {
    __shared__ int ws[32];
    int tid = threadIdx.x;
    int i = blockIdx.x * 1024 + tid;
    int v = (i < NN) ? g_deg[i] : 0;
    if (i < NN) g_dis[i] = rsqrtf(1.f + (float)v);
    int s = v;
#pragma unroll
    for (int off = 16; off; off >>= 1) s += __shfl_xor_sync(0xFFFFFFFFu, s, off);
    if ((tid & 31) == 0) ws[tid >> 5] = s;
    __syncthreads();
    if (tid < 32) {
        int t = ws[tid];
#pragma unroll
        for (int off = 16; off; off >>= 1) t += __shfl_xor_sync(0xFFFFFFFFu, t, off);
        if (tid == 0) g_bsum[blockIdx.x] = t;
    }
}

// rowptr with inlined block-offset reduction + cursor zeroing
__global__ void rowptr_kernel() {
    __shared__ int ws[32];
    __shared__ int sboff[2];
    int tid = threadIdx.x, lane = tid & 31, w = tid >> 5;
    if (w < 2) {
        int idx = w * 32 + lane;
        int bv = (idx < NB && idx < blockIdx.x) ? g_bsum[idx] : 0;
#pragma unroll
        for (int off = 16; off; off >>= 1) bv += __shfl_xor_sync(0xFFFFFFFFu, bv, off);
        if (lane == 0) sboff[w] = bv;
    }
    int i = blockIdx.x * 1024 + tid;
    if (i < NN) g_cursor[i] = 0;
    int v = (i < NN) ? g_deg[i] : 0;
    int x = v;
#pragma unroll
    for (int off = 1; off < 32; off <<= 1) {
        int t = __shfl_up_sync(0xFFFFFFFFu, x, off);
        if (lane >= off) x += t;
    }
    if (lane == 31) ws[w] = x;
    __syncthreads();
    if (tid < 32) {
        int y = ws[tid];
#pragma unroll
        for (int off = 1; off < 32; off <<= 1) {
            int t = __shfl_up_sync(0xFFFFFFFFu, y, off);
            if (tid >= off) y += t;
        }
        ws[tid] = y;
    }
    __syncthreads();
    int boff = sboff[0] + sboff[1];
    int incl = x + (w > 0 ? ws[w - 1] : 0) + boff;
    if (i < NN) g_rowptr[i + 1] = incl;
    if (i == 0) g_rowptr[0] = 0;
}

__global__ void fill_kernel(const int* __restrict__ src, const int* __restrict__ dst) {
    int i = blockIdx.x * blockDim.x + threadIdx.x;
    if (i < EE) {
        int d = dst[i];
        int pos = atomicAdd(&g_cursor[d], 1);
        g_col[g_rowptr[d] + pos] = src[i];
    }
}

// ---------------- fp32 -> bf16 hi/lo split (vectorized: 4 elems/thread) ----------------
__global__ void split_kernel(const float4* __restrict__ in, uint2* __restrict__ hi,
                             uint2* __restrict__ lo, int count4) {
    int i = blockIdx.x * blockDim.x + threadIdx.x;
    if (i < count4) {
        float4 v = in[i];
        __nv_bfloat16 h0 = __float2bfloat16_rn(v.x);
        __nv_bfloat16 h1 = __float2bfloat16_rn(v.y);
        __nv_bfloat16 h2 = __float2bfloat16_rn(v.z);
        __nv_bfloat16 h3 = __float2bfloat16_rn(v.w);
        __nv_bfloat162 t;
        uint2 ph, pl;
        t.x = h0; t.y = h1; ph.x = *reinterpret_cast<uint32_t*>(&t);
        t.x = h2; t.y = h3; ph.y = *reinterpret_cast<uint32_t*>(&t);
        t.x = __float2bfloat16_rn(v.x - __bfloat162float(h0));
        t.y = __float2bfloat16_rn(v.y - __bfloat162float(h1));
        pl.x = *reinterpret_cast<uint32_t*>(&t);
        t.x = __float2bfloat16_rn(v.z - __bfloat162float(h2));
        t.y = __float2bfloat16_rn(v.w - __bfloat162float(h3));
        pl.y = *reinterpret_cast<uint32_t*>(&t);
        hi[i] = ph;
        lo[i] = pl;
    }
}

__global__ void wsplit_all_kernel(const float* __restrict__ W1, const float* __restrict__ Wr,
                                  const float* __restrict__ W2, const float* __restrict__ W3,
                                  const float* __restrict__ W4,
                                  __nv_bfloat16* __restrict__ th, __nv_bfloat16* __restrict__ tl) {
    int i = blockIdx.x * blockDim.x + threadIdx.x;
    if (i >= 196608) return;
    const float* W; int off, K, N, j;
    if (i < 8192)        { W = W1; off = 0;      K = 128; N = 64;  j = i; }
    else if (i < 16384)  { W = Wr; off = 8192;   K = 128; N = 64;  j = i - 8192; }
    else if (i < 32768)  { W = W2; off = 16384;  K = 64;  N = 256; j = i - 16384; }
    else if (i < 163840) { W = W3; off = 32768;  K = 256; N = 512; j = i - 32768; }
    else                 { W = W4; off = 163840; K = 512; N = 64;  j = i - 163840; }
    int k = j / N, n = j % N;
    float v = W[j];
    __nv_bfloat16 h = __float2bfloat16_rn(v);
    th[off + n * K + k] = h;
    tl[off + n * K + k] = __float2bfloat16_rn(v - __bfloat162float(h));
}

// ---------------- PTX helpers ----------------
__device__ __forceinline__ void mma_bf16(float* c, const uint32_t* a, const uint32_t* b) {
    asm volatile(
        "mma.sync.aligned.m16n8k16.row.col.f32.bf16.bf16.f32 "
        "{%0,%1,%2,%3}, {%4,%5,%6,%7}, {%8,%9}, {%0,%1,%2,%3};"
        : "+f"(c[0]), "+f"(c[1]), "+f"(c[2]), "+f"(c[3])
        : "r"(a[0]), "r"(a[1]), "r"(a[2]), "r"(a[3]), "r"(b[0]), "r"(b[1]));
}
__device__ __forceinline__ void ldsm4(uint32_t* r, uint32_t addr) {
    asm volatile("ldmatrix.sync.aligned.m8n8.x4.shared.b16 {%0,%1,%2,%3}, [%4];"
                 : "=r"(r[0]), "=r"(r[1]), "=r"(r[2]), "=r"(r[3]) : "r"(addr));
}
__device__ __forceinline__ void cp16(uint32_t saddr, const void* g, bool valid) {
    int sz = valid ? 16 : 0;
    asm volatile("cp.async.cg.shared.global [%0], [%1], 16, %2;\n"
                 :: "r"(saddr), "l"(g), "r"(sz));
}
__device__ __forceinline__ void cp_commit() {
    asm volatile("cp.async.commit_group;\n" ::: "memory");
}
template <int N>
__device__ __forceinline__ void cp_wait() {
    asm volatile("cp.async.wait_group %0;\n" :: "n"(N) : "memory");
}

// ---------------- 2-stage pipelined split-bf16 HMMA GEMM (2 CTAs/SM, BM=128) ----------------
template <int K, int NCOLS, bool BIAS, bool SPLIT_EPI, bool DUAL, bool ROW_SCALE>
__global__ __launch_bounds__(256, 2)
void mm_kernel(const __nv_bfloat16* __restrict__ Ah, const __nv_bfloat16* __restrict__ Al,
               const __nv_bfloat16* __restrict__ Bh, const __nv_bfloat16* __restrict__ Bl,
               const float* __restrict__ bias, float* __restrict__ C,
               __nv_bfloat16* __restrict__ Chi, __nv_bfloat16* __restrict__ Clo,
               float* __restrict__ C2, int M) {
    constexpr int BM = 128;
    constexpr int BN = (NCOLS < 128) ? NCOLS : 128;
    constexpr int BK = 32;
    constexpr int SA = BK + 8;
    constexpr int WM = (BN == 64) ? 32 : 64;
    constexpr int WN = 32;
    constexpr int WGN = BN / WN;
    constexpr int MFR = WM / 16;
    constexpr int NFR = WN / 8;
    constexpr int NT = K / BK;
    constexpr int STG = 2 * (BM + BN) * SA;

    extern __shared__ __nv_bfloat16 smem[];
    const uint32_t sbase = (uint32_t)__cvta_generic_to_shared(smem);

    const int tid = threadIdx.x, wid = tid >> 5, lane = tid & 31;
    const int warp_m = wid / WGN, warp_n = wid % WGN;
    const int rowBase = blockIdx.x * BM;
    const int colBase = blockIdx.y * BN;
    const int gID = lane >> 2, tig = lane & 3;

    float acc[MFR][NFR][4] = {};

    auto load_stage = [&](int k0, int st) {
        const int aoff = st * STG;
#pragma unroll
        for (int i = tid; i < BM * 4; i += 256) {
            int r = i >> 2, q = i & 3;
            int gr = rowBase + r;
            bool ok = gr < M;
            size_t go = (size_t)(ok ? gr : 0) * K + k0 + q * 8;
            uint32_t sa = sbase + (uint32_t)(aoff + r * SA + q * 8) * 2;
            cp16(sa, Ah + go, ok);
            cp16(sa + (uint32_t)(BM * SA) * 2, Al + go, ok);
        }
        const int boff = st * STG + 2 * BM * SA;
#pragma unroll
        for (int i = tid; i < BN * 4; i += 256) {
            int r = i >> 2, q = i & 3;
            size_t go = (size_t)(colBase + r) * K + k0 + q * 8;
            uint32_t sa = sbase + (uint32_t)(boff + r * SA + q * 8) * 2;
            cp16(sa, Bh + go, true);
            cp16(sa + (uint32_t)(BN * SA) * 2, Bl + go, true);
        }
        cp_commit();
    };

    load_stage(0, 0);
    if (NT > 1) load_stage(BK, 1);

    for (int kt = 0; kt < NT; kt++) {
        if (kt + 1 < NT) cp_wait<1>(); else cp_wait<0>();
        __syncthreads();

        const int st = kt & 1;
        const uint32_t ah_base = sbase + (uint32_t)(st * STG) * 2;
        const uint32_t al_base = ah_base + (uint32_t)(BM * SA) * 2;
        const uint32_t bh_base = ah_base + (uint32_t)(2 * BM * SA) * 2;
        const uint32_t bl_base = bh_base + (uint32_t)(BN * SA) * 2;

#pragma unroll
        for (int kk = 0; kk < BK; kk += 16) {
            uint32_t bfh[NFR][2], bfl[NFR][2];
            int bn = warp_n * WN + ((lane >> 4) << 3) + (lane & 7);
            int bk = kk + ((lane >> 3) & 1) * 8;
#pragma unroll
            for (int pr = 0; pr < NFR / 2; pr++) {
                uint32_t off = (uint32_t)((bn + pr * 16) * SA + bk) * 2;
                uint32_t rh[4], rl[4];
                ldsm4(rh, bh_base + off);
                ldsm4(rl, bl_base + off);
                bfh[pr * 2][0] = rh[0]; bfh[pr * 2][1] = rh[1];
                bfh[pr * 2 + 1][0] = rh[2]; bfh[pr * 2 + 1][1] = rh[3];
                bfl[pr * 2][0] = rl[0]; bfl[pr * 2][1] = rl[1];
                bfl[pr * 2 + 1][0] = rl[2]; bfl[pr * 2 + 1][1] = rl[3];
            }
            int arow = warp_m * WM + (lane & 15);
            int acol = kk + ((lane >> 4) << 3);
#pragma unroll
            for (int mf = 0; mf < MFR; mf++) {
                uint32_t afh[4], afl[4];
                uint32_t off = (uint32_t)((arow + mf * 16) * SA + acol) * 2;
                ldsm4(afh, ah_base + off);
                ldsm4(afl, al_base + off);
#pragma unroll
                for (int nf = 0; nf < NFR; nf++) {
                    mma_bf16(acc[mf][nf], afh, bfh[nf]);
                    mma_bf16(acc[mf][nf], afh, bfl[nf]);
                    mma_bf16(acc[mf][nf], afl, bfh[nf]);
                }
            }
        }
        if (kt + 2 < NT) {
            __syncthreads();
            load_stage((kt + 2) * BK, st);
        }
    }

    // ---- epilogue ----
#pragma unroll
    for (int mf = 0; mf < MFR; mf++) {
        int r0 = rowBase + warp_m * WM + mf * 16 + gID;
        float d0 = 1.f, d1 = 1.f;
        if (ROW_SCALE) {
            d0 = (r0 < M) ? g_dis[r0] : 0.f;
            d1 = (r0 + 8 < M) ? g_dis[r0 + 8] : 0.f;
        }
#pragma unroll
        for (int nf = 0; nf < NFR; nf++) {
            int col = colBase + warp_n * WN + nf * 8 + tig * 2;
            float v0 = acc[mf][nf][0], v1 = acc[mf][nf][1];
            float v2 = acc[mf][nf][2], v3 = acc[mf][nf][3];
            if (DUAL) {
                if (col < 64) {
                    if (r0 < M)
                        *reinterpret_cast<float2*>(C + (size_t)r0 * 64 + col) = make_float2(v0, v1);
                    if (r0 + 8 < M)
                        *reinterpret_cast<float2*>(C + (size_t)(r0 + 8) * 64 + col) = make_float2(v2, v3);
                } else {
                    int c2 = col - 64;
                    float bb0 = bias[c2], bb1 = bias[c2 + 1];
                    v0 += bb0; v1 += bb1; v2 += bb0; v3 += bb1;
                    if (r0 < M)
                        *reinterpret_cast<float2*>(C2 + (size_t)r0 * 64 + c2) = make_float2(v0, v1);
                    if (r0 + 8 < M)
                        *reinterpret_cast<float2*>(C2 + (size_t)(r0 + 8) * 64 + c2) = make_float2(v2, v3);
                }
                continue;
            }
            if (BIAS) {
                float bb0 = bias[col], bb1 = bias[col + 1];
                v0 += bb0; v1 += bb1; v2 += bb0; v3 += bb1;
            }
            if (ROW_SCALE) { v0 *= d0; v1 *= d0; v2 *= d1; v3 *= d1; }
            if (SPLIT_EPI) {
                v0 = lrelu(v0); v1 = lrelu(v1); v2 = lrelu(v2); v3 = lrelu(v3);
                if (r0 < M) {
                    __nv_bfloat16 h0 = __float2bfloat16_rn(v0);
                    __nv_bfloat16 h1 = __float2bfloat16_rn(v1);
                    __nv_bfloat162 ph, pl;
                    ph.x = h0; ph.y = h1;
                    pl.x = __float2bfloat16_rn(v0 - __bfloat162float(h0));
                    pl.y = __float2bfloat16_rn(v1 - __bfloat162float(h1));
                    *reinterpret_cast<__nv_bfloat162*>(Chi + (size_t)r0 * NCOLS + col) = ph;
                    *reinterpret_cast<__nv_bfloat162*>(Clo + (size_t)r0 * NCOLS + col) = pl;
                }
                if (r0 + 8 < M) {
                    __nv_bfloat16 h2 = __float2bfloat16_rn(v2);
                    __nv_bfloat16 h3 = __float2bfloat16_rn(v3);
                    __nv_bfloat162 ph, pl;
                    ph.x = h2; ph.y = h3;
                    pl.x = __float2bfloat16_rn(v2 - __bfloat162float(h2));
                    pl.y = __float2bfloat16_rn(v3 - __bfloat162float(h3));
                    *reinterpret_cast<__nv_bfloat162*>(Chi + (size_t)(r0 + 8) * NCOLS + col) = ph;
                    *reinterpret_cast<__nv_bfloat162*>(Clo + (size_t)(r0 + 8) * NCOLS + col) = pl;
                }
            } else {
                if (r0 < M)
                    *reinterpret_cast<float2*>(C + (size_t)r0 * NCOLS + col) = make_float2(v0, v1);
                if (r0 + 8 < M)
                    *reinterpret_cast<float2*>(C + (size_t)(r0 + 8) * NCOLS + col) = make_float2(v2, v3);
            }
        }
    }
}

// ---------------- CSR gather aggregation ----------------
template <int F, bool LEAKY, bool BIAS, bool SPLIT, bool PRESCALED, bool OUTSCALE>
__global__ __launch_bounds__(256)
void agg_kernel(const float* __restrict__ in, float* __restrict__ out,
                const float* __restrict__ bias,
                __nv_bfloat16* __restrict__ oh, __nv_bfloat16* __restrict__ ol) {
    int warp = (blockIdx.x * 256 + threadIdx.x) >> 5;
    int lane = threadIdx.x & 31;
    if (warp >= NN) return;
    const int n = warp;
    const float dn = g_dis[n];
    constexpr int R = F / 32;
    float acc[R];
    const float wself = PRESCALED ? 1.f : dn * dn;
#pragma unroll
    for (int r = 0; r < R; r++) {
        float v = in[(size_t)n * F + lane + r * 32];
        if (LEAKY) v = lrelu(v);
        acc[r] = v * wself;
    }
    const int e0 = g_rowptr[n], e1 = g_rowptr[n + 1];
    int e = e0;
    for (; e + 3 < e1; e += 4) {
        int s0 = g_col[e], s1 = g_col[e + 1], s2 = g_col[e + 2], s3 = g_col[e + 3];
        float w0 = 1.f, w1 = 1.f, w2 = 1.f, w3 = 1.f;
        if (!PRESCALED) {
            w0 = g_dis[s0] * dn; w1 = g_dis[s1] * dn;
            w2 = g_dis[s2] * dn; w3 = g_dis[s3] * dn;
        }
#pragma unroll
        for (int r = 0; r < R; r++) {
            float va = in[(size_t)s0 * F + lane + r * 32];
            float vb = in[(size_t)s1 * F + lane + r * 32];
            float vc = in[(size_t)s2 * F + lane + r * 32];
            float vd = in[(size_t)s3 * F + lane + r * 32];
            if (LEAKY) { va = lrelu(va); vb = lrelu(vb); vc = lrelu(vc); vd = lrelu(vd); }
            if (PRESCALED) acc[r] += (va + vb) + (vc + vd);
            else acc[r] += va * w0 + vb * w1 + vc * w2 + vd * w3;
        }
    }
    for (; e < e1; e++) {
        int s0 = g_col[e];
        float w0 = PRESCALED ? 1.f : g_dis[s0] * dn;
#pragma unroll
        for (int r = 0; r < R; r++) {
            float va = in[(size_t)s0 * F + lane + r * 32];
            if (LEAKY) va = lrelu(va);
            acc[r] += PRESCALED ? va : va * w0;
        }
    }
#pragma unroll
    for (int r = 0; r < R; r++) {
        float o = acc[r];
        if (BIAS) o += bias[lane + r * 32];
        if (PRESCALED || OUTSCALE) o *= dn;
        if (SPLIT) {
            __nv_bfloat16 h = __float2bfloat16_rn(o);
            oh[(size_t)n * F + lane + r * 32] = h;
            ol[(size_t)n * F + lane + r * 32] = __float2bfloat16_rn(o - __bfloat162float(h));
        } else {
            out[(size_t)n * F + lane + r * 32] = o;
        }
    }
}

// ---------------- fused L4 agg (prescaled input) + bias + leaky + residual + layernorm ----------------
__global__ __launch_bounds__(256)
void agg_ln_kernel(const float* __restrict__ q4, const float* __restrict__ b4,
                   const float* __restrict__ resid,
                   const float* __restrict__ gamma, const float* __restrict__ beta,
                   float* __restrict__ z) {
    int warp = (blockIdx.x * 256 + threadIdx.x) >> 5;
    int lane = threadIdx.x & 31;
    if (warp >= NN) return;
    const int n = warp;
    const float dn = g_dis[n];
    float a0 = q4[(size_t)n * 64 + lane];
    float a1 = q4[(size_t)n * 64 + lane + 32];
    const int e0 = g_rowptr[n], e1 = g_rowptr[n + 1];
    int e = e0;
    for (; e + 3 < e1; e += 4) {
        int s0 = g_col[e], s1 = g_col[e + 1], s2 = g_col[e + 2], s3 = g_col[e + 3];
        a0 += (q4[(size_t)s0 * 64 + lane] + q4[(size_t)s1 * 64 + lane])
            + (q4[(size_t)s2 * 64 + lane] + q4[(size_t)s3 * 64 + lane]);
        a1 += (q4[(size_t)s0 * 64 + lane + 32] + q4[(size_t)s1 * 64 + lane + 32])
            + (q4[(size_t)s2 * 64 + lane + 32] + q4[(size_t)s3 * 64 + lane + 32]);
    }
    for (; e < e1; e++) {
        int s0 = g_col[e];
        a0 += q4[(size_t)s0 * 64 + lane];
        a1 += q4[(size_t)s0 * 64 + lane + 32];
    }
    float v0 = lrelu(a0 * dn + b4[lane]) + resid[(size_t)n * 64 + lane];
    float v1 = lrelu(a1 * dn + b4[lane + 32]) + resid[(size_t)n * 64 + lane + 32];
    float s = v0 + v1, sq = v0 * v0 + v1 * v1;
#pragma unroll
    for (int off = 16; off; off >>= 1) {
        s += __shfl_xor_sync(0xFFFFFFFFu, s, off);
        sq += __shfl_xor_sync(0xFFFFFFFFu, sq, off);
    }
    float mean = s * (1.f / 64.f);
    float var = sq * (1.f / 64.f) - mean * mean;
    float inv = rsqrtf(var + 1e-5f);
    z[(size_t)n * 64 + lane]      = (v0 - mean) * inv * gamma[lane]      + beta[lane];
    z[(size_t)n * 64 + lane + 32] = (v1 - mean) * inv * gamma[lane + 32] + beta[lane + 32];
}

// ---------------- pool stage 1 ----------------
__global__ void pool1_kernel(const float* __restrict__ z) {
    int g = blockIdx.x, part = blockIdx.y, j = threadIdx.x;
    int s = (g * NN + GG - 1) / GG;
    int e = ((g + 1) * NN + GG - 1) / GG;
    int cnt = e - s;
    int ps = s + (cnt * part) / 16;
    int pe = s + (cnt * (part + 1)) / 16;
    float m = -3.402823e38f;
    for (int n = ps; n < pe; n++) m = fmaxf(m, z[(size_t)n * 64 + j]);
    g_pp[(g * 16 + part) * 64 + j] = m;
}

// ---------------- fused pool stage 2 + head ----------------
__global__ void head_kernel(const float* __restrict__ fc1W, const float* __restrict__ fc1b,
                            const float* __restrict__ fng, const float* __restrict__ fnb,
                            const float* __restrict__ fc2W, const float* __restrict__ fc2b,
                            float* __restrict__ out) {
    __shared__ float ps[64];
    __shared__ float q[64];
    __shared__ float red[64];
    int g = blockIdx.x, j = threadIdx.x;
    float m = -3.402823e38f;
#pragma unroll
    for (int part = 0; part < 16; part++)
        m = fmaxf(m, g_pp[(g * 16 + part) * 64 + j]);
    ps[j] = m;
    __syncthreads();
    float acc = fc1b[j];
#pragma unroll 8
    for (int k = 0; k < 64; k++) acc += ps[k] * fc1W[k * 64 + j];
    red[j] = acc;
    __syncthreads();
#pragma unroll
    for (int off = 32; off; off >>= 1) { if (j < off) red[j] += red[j + off]; __syncthreads(); }
    float mean = red[0] * (1.f / 64.f);
    __syncthreads();
    float d = acc - mean;
    red[j] = d * d;
    __syncthreads();
#pragma unroll
    for (int off = 32; off; off >>= 1) { if (j < off) red[j] += red[j + off]; __syncthreads(); }
    float var = red[0] * (1.f / 64.f);
    float qn = d * rsqrtf(var + 1e-5f) * fng[j] + fnb[j];
    q[j] = lrelu(qn);
    __syncthreads();
    if (j < 16) {
        float o = fc2b[j];
#pragma unroll 8
        for (int k = 0; k < 64; k++) o += q[k] * fc2W[k * 16 + j];
        out[g * 16 + j] = o;
    }
}

// ---------------- launcher ----------------
static inline int mm_smem_bytes(int bn) { return 2 * 2 * (128 + bn) * 40 * 2; }

extern "C" void kernel_launch(void* const* d_in, const int* in_sizes, int n_in,
                              void* d_out, int out_size) {
    (void)in_sizes; (void)n_in; (void)out_size;
    const float* x   = (const float*)d_in[0];
    const int*   ei  = (const int*)d_in[1];
    const float *W1 = (const float*)d_in[3],  *b1 = (const float*)d_in[4];
    const float *W2 = (const float*)d_in[5],  *b2 = (const float*)d_in[6];
    const float *W3 = (const float*)d_in[7],  *b3 = (const float*)d_in[8];
    const float *W4 = (const float*)d_in[9],  *b4 = (const float*)d_in[10];
    const float *Wr = (const float*)d_in[11], *br = (const float*)d_in[12];
    const float *lng = (const float*)d_in[13], *lnb = (const float*)d_in[14];
    const float *fc1W = (const float*)d_in[15], *fc1b = (const float*)d_in[16];
    const float *fng = (const float*)d_in[17], *fnb = (const float*)d_in[18];
    const float *fc2W = (const float*)d_in[19], *fc2b = (const float*)d_in[20];
    float* out = (float*)d_out;

    float *bufA, *bufB, *resid;
    __nv_bfloat16 *ah, *al, *bh, *bl, *xh, *xl, *wh, *wl;
    cudaGetSymbolAddress((void**)&bufA, g_bufA);
    cudaGetSymbolAddress((void**)&bufB, g_bufB);
    cudaGetSymbolAddress((void**)&resid, g_resid);
    cudaGetSymbolAddress((void**)&ah, g_ah);
    cudaGetSymbolAddress((void**)&al, g_al);
    cudaGetSymbolAddress((void**)&bh, g_bh);
    cudaGetSymbolAddress((void**)&bl, g_bl);
    cudaGetSymbolAddress((void**)&xh, g_xh);
    cudaGetSymbolAddress((void**)&xl, g_xl);
    cudaGetSymbolAddress((void**)&wh, g_wh);
    cudaGetSymbolAddress((void**)&wl, g_wl);

    __nv_bfloat16 *w1h = wh + 0,      *w1l = wl + 0;
    __nv_bfloat16 *w2h = wh + 16384,  *w2l = wl + 16384;
    __nv_bfloat16 *w3h = wh + 32768,  *w3l = wl + 32768;
    __nv_bfloat16 *w4h = wh + 163840, *w4l = wl + 163840;

    const int* src = ei;
    const int* dst = ei + EE;

    cudaFuncSetAttribute(mm_kernel<128, 128, false, false, true, false>, cudaFuncAttributeMaxDynamicSharedMemorySize, mm_smem_bytes(128));
    cudaFuncSetAttribute(mm_kernel<64, 256, true, false, false, true>,   cudaFuncAttributeMaxDynamicSharedMemorySize, mm_smem_bytes(128));
    cudaFuncSetAttribute(mm_kernel<256, 512, true, true, false, false>,  cudaFuncAttributeMaxDynamicSharedMemorySize, mm_smem_bytes(128));
    cudaFuncSetAttribute(mm_kernel<512, 64, false, false, false, true>,  cudaFuncAttributeMaxDynamicSharedMemorySize, mm_smem_bytes(64));

    // side stream + events (host objects, created once)
    static cudaStream_t s2 = nullptr;
    static cudaEvent_t evFork = nullptr, evJoin = nullptr, evW = nullptr;
    if (s2 == nullptr) {
        cudaStreamCreateWithFlags(&s2, cudaStreamNonBlocking);
        cudaEventCreateWithFlags(&evFork, cudaEventDisableTiming);
        cudaEventCreateWithFlags(&evJoin, cudaEventDisableTiming);
        cudaEventCreateWithFlags(&evW, cudaEventDisableTiming);
    }

    const int MT = (NN + 127) / 128;
    const int AGG_BLOCKS = (NN + 7) / 8;

    // ---- fork ----
    cudaEventRecord(evFork, 0);
    cudaStreamWaitEvent(s2, evFork, 0);

    // s2 branch: weight split first (gates mm_L1), then CSR chain
    wsplit_all_kernel<<<(196608 + 255) / 256, 256, 0, s2>>>(W1, Wr, W2, W3, W4, wh, wl);
    cudaEventRecord(evW, s2);
    zero_kernel<<<(NN + 255) / 256, 256, 0, s2>>>();
    count_deg_kernel<<<(EE + 255) / 256, 256, 0, s2>>>(dst);
    bsum_kernel<<<NB, 1024, 0, s2>>>();
    rowptr_kernel<<<NB, 1024, 0, s2>>>();
    fill_kernel<<<(EE + 255) / 256, 256, 0, s2>>>(src, dst);
    cudaEventRecord(evJoin, s2);

    // legacy branch: x split, then (after weights ready) L1 GEMM
    split_kernel<<<(NN * 32 + 255) / 256, 256>>>(
        reinterpret_cast<const float4*>(x), reinterpret_cast<uint2*>(xh),
        reinterpret_cast<uint2*>(xl), NN * 32);
    cudaStreamWaitEvent(0, evW, 0);
    mm_kernel<128, 128, false, false, true, false><<<dim3(MT, 1), 256, mm_smem_bytes(128)>>>(
        xh, xl, w1h, w1l, br, bufA, nullptr, nullptr, resid, NN);

    // ---- join ----
    cudaStreamWaitEvent(0, evJoin, 0);

    // agg1: q1 = dis[n]*(agg(t1)+b1)
    agg_kernel<64, false, true, false, false, true><<<AGG_BLOCKS, 256>>>(bufA, bufB, b1, nullptr, nullptr);
    // agg2 (prescaled): g2 -> split
    agg_kernel<64, true, false, true, true, false><<<AGG_BLOCKS, 256>>>(bufB, nullptr, nullptr, ah, al);
    // L2 GEMM with ROW_SCALE
    mm_kernel<64, 256, true, false, false, true><<<dim3(MT, 2), 256, mm_smem_bytes(128)>>>(
        ah, al, w2h, w2l, b2, bufB, nullptr, nullptr, nullptr, NN);
    // agg3 (prescaled): g3 -> split
    agg_kernel<256, true, false, true, true, false><<<AGG_BLOCKS, 256>>>(bufB, nullptr, nullptr, ah, al);
    // L3 GEMM (split epilogue)
    mm_kernel<256, 512, true, true, false, false><<<dim3(MT, 4), 256, mm_smem_bytes(128)>>>(
        ah, al, w3h, w3l, b3, nullptr, bh, bl, nullptr, NN);
    // L4 GEMM with ROW_SCALE
    mm_kernel<512, 64, false, false, false, true><<<dim3(MT, 1), 256, mm_smem_bytes(64)>>>(
        bh, bl, w4h, w4l, nullptr, bufA, nullptr, nullptr, nullptr, NN);
    // fused agg (prescaled) + bias + leaky + residual + LN
    agg_ln_kernel<<<AGG_BLOCKS, 256>>>(bufA, b4, resid, lng, lnb, bufB);
    // pool + fused head
    pool1_kernel<<<dim3(GG, 16), 64>>>(bufB);
    head_kernel<<<GG, 64>>>(fc1W, fc1b, fng, fnb, fc2W, fc2b, out);
}

// round 16
// speedup vs baseline: 1.0862x; 1.0079x over previous
#include <cuda_runtime.h>
#include <cuda_bf16.h>
#include <cstdint>

#define NN 50000
#define EE 400000
#define GG 64
#define NB 49   // ceil(NN/1024)

// ---------------- scratch (static device globals; no allocs) ----------------
__device__ float g_bufA[NN * 512];
__device__ float g_bufB[NN * 512];
__device__ float g_resid[NN * 64];
__device__ float g_pp[GG * 16 * 64];
__device__ float g_dis[NN];
__device__ int   g_deg[NN];
__device__ int   g_rowptr[NN + 1];
__device__ int   g_cursor[NN];
__device__ int   g_col[EE];
__device__ int   g_bsum[64];
__device__ __nv_bfloat16 g_ah[NN * 512];
__device__ __nv_bfloat16 g_al[NN * 512];
__device__ __nv_bfloat16 g_bh[NN * 512];
__device__ __nv_bfloat16 g_bl[NN * 512];
__device__ __nv_bfloat16 g_xh[NN * 128];
__device__ __nv_bfloat16 g_xl[NN * 128];
__device__ __nv_bfloat16 g_wh[262144];
__device__ __nv_bfloat16 g_wl[262144];

__device__ __forceinline__ float lrelu(float v) { return v >= 0.f ? v : 0.01f * v; }

// ---------------- CSR build ----------------
__global__ void zero_kernel() {
    int i = blockIdx.x * blockDim.x + threadIdx.x;
    if (i < NN) g_deg[i] = 0;
}

__global__ void count_deg_kernel(const int* __restrict__ dst) {
    int i = blockIdx.x * blockDim.x + threadIdx.x;
    if (i < EE) atomicAdd(&g_deg[dst[i]], 1);
}

__global__ void bsum_kernel() {
    __shared__ int ws[32];
    int tid = threadIdx.x;
    int i = blockIdx.x * 1024 + tid;
    int v = (i < NN) ? g_deg[i] : 0;
    if (i < NN) g_dis[i] = rsqrtf(1.f + (float)v);
    int s = v;
#pragma unroll
    for (int off = 16; off; off >>= 1) s += __shfl_xor_sync(0xFFFFFFFFu, s, off);
    if ((tid & 31) == 0) ws[tid >> 5] = s;
    __syncthreads();
    if (tid < 32) {
        int t = ws[tid];
#pragma unroll
        for (int off = 16; off; off >>= 1) t += __shfl_xor_sync(0xFFFFFFFFu, t, off);
        if (tid == 0) g_bsum[blockIdx.x] = t;
    }
}

// rowptr with inlined block-offset reduction + cursor zeroing
__global__ void rowptr_kernel() {
    __shared__ int ws[32];
    __shared__ int sboff[2];
    int tid = threadIdx.x, lane = tid & 31, w = tid >> 5;
    if (w < 2) {
        int idx = w * 32 + lane;
        int bv = (idx < NB && idx < blockIdx.x) ? g_bsum[idx] : 0;
#pragma unroll
        for (int off = 16; off; off >>= 1) bv += __shfl_xor_sync(0xFFFFFFFFu, bv, off);
        if (lane == 0) sboff[w] = bv;
    }
    int i = blockIdx.x * 1024 + tid;
    if (i < NN) g_cursor[i] = 0;
    int v = (i < NN) ? g_deg[i] : 0;
    int x = v;
#pragma unroll
    for (int off = 1; off < 32; off <<= 1) {
        int t = __shfl_up_sync(0xFFFFFFFFu, x, off);
        if (lane >= off) x += t;
    }
    if (lane == 31) ws[w] = x;
    __syncthreads();
    if (tid < 32) {
        int y = ws[tid];
#pragma unroll
        for (int off = 1; off < 32; off <<= 1) {
            int t = __shfl_up_sync(0xFFFFFFFFu, y, off);
            if (tid >= off) y += t;
        }
        ws[tid] = y;
    }
    __syncthreads();
    int boff = sboff[0] + sboff[1];
    int incl = x + (w > 0 ? ws[w - 1] : 0) + boff;
    if (i < NN) g_rowptr[i + 1] = incl;
    if (i == 0) g_rowptr[0] = 0;
}

__global__ void fill_kernel(const int* __restrict__ src, const int* __restrict__ dst) {
    int i = blockIdx.x * blockDim.x + threadIdx.x;
    if (i < EE) {
        int d = dst[i];
        int pos = atomicAdd(&g_cursor[d], 1);
        g_col[g_rowptr[d] + pos] = src[i];
    }
}

// ---------------- fp32 -> bf16 hi/lo split (vectorized: 4 elems/thread) ----------------
__global__ void split_kernel(const float4* __restrict__ in, uint2* __restrict__ hi,
                             uint2* __restrict__ lo, int count4) {
    int i = blockIdx.x * blockDim.x + threadIdx.x;
    if (i < count4) {
        float4 v = in[i];
        __nv_bfloat16 h0 = __float2bfloat16_rn(v.x);
        __nv_bfloat16 h1 = __float2bfloat16_rn(v.y);
        __nv_bfloat16 h2 = __float2bfloat16_rn(v.z);
        __nv_bfloat16 h3 = __float2bfloat16_rn(v.w);
        __nv_bfloat162 t;
        uint2 ph, pl;
        t.x = h0; t.y = h1; ph.x = *reinterpret_cast<uint32_t*>(&t);
        t.x = h2; t.y = h3; ph.y = *reinterpret_cast<uint32_t*>(&t);
        t.x = __float2bfloat16_rn(v.x - __bfloat162float(h0));
        t.y = __float2bfloat16_rn(v.y - __bfloat162float(h1));
        pl.x = *reinterpret_cast<uint32_t*>(&t);
        t.x = __float2bfloat16_rn(v.z - __bfloat162float(h2));
        t.y = __float2bfloat16_rn(v.w - __bfloat162float(h3));
        pl.y = *reinterpret_cast<uint32_t*>(&t);
        hi[i] = ph;
        lo[i] = pl;
    }
}

__global__ void wsplit_all_kernel(const float* __restrict__ W1, const float* __restrict__ Wr,
                                  const float* __restrict__ W2, const float* __restrict__ W3,
                                  const float* __restrict__ W4,
                                  __nv_bfloat16* __restrict__ th, __nv_bfloat16* __restrict__ tl) {
    int i = blockIdx.x * blockDim.x + threadIdx.x;
    if (i >= 196608) return;
    const float* W; int off, K, N, j;
    if (i < 8192)        { W = W1; off = 0;      K = 128; N = 64;  j = i; }
    else if (i < 16384)  { W = Wr; off = 8192;   K = 128; N = 64;  j = i - 8192; }
    else if (i < 32768)  { W = W2; off = 16384;  K = 64;  N = 256; j = i - 16384; }
    else if (i < 163840) { W = W3; off = 32768;  K = 256; N = 512; j = i - 32768; }
    else                 { W = W4; off = 163840; K = 512; N = 64;  j = i - 163840; }
    int k = j / N, n = j % N;
    float v = W[j];
    __nv_bfloat16 h = __float2bfloat16_rn(v);
    th[off + n * K + k] = h;
    tl[off + n * K + k] = __float2bfloat16_rn(v - __bfloat162float(h));
}

// ---------------- PTX helpers ----------------
__device__ __forceinline__ void mma_bf16(float* c, const uint32_t* a, const uint32_t* b) {
    asm volatile(
        "mma.sync.aligned.m16n8k16.row.col.f32.bf16.bf16.f32 "
        "{%0,%1,%2,%3}, {%4,%5,%6,%7}, {%8,%9}, {%0,%1,%2,%3};"
        : "+f"(c[0]), "+f"(c[1]), "+f"(c[2]), "+f"(c[3])
        : "r"(a[0]), "r"(a[1]), "r"(a[2]), "r"(a[3]), "r"(b[0]), "r"(b[1]));
}
__device__ __forceinline__ void ldsm4(uint32_t* r, uint32_t addr) {
    asm volatile("ldmatrix.sync.aligned.m8n8.x4.shared.b16 {%0,%1,%2,%3}, [%4];"
                 : "=r"(r[0]), "=r"(r[1]), "=r"(r[2]), "=r"(r[3]) : "r"(addr));
}
__device__ __forceinline__ void cp16(uint32_t saddr, const void* g, bool valid) {
    int sz = valid ? 16 : 0;
    asm volatile("cp.async.cg.shared.global [%0], [%1], 16, %2;\n"
                 :: "r"(saddr), "l"(g), "r"(sz));
}
__device__ __forceinline__ void cp_commit() {
    asm volatile("cp.async.commit_group;\n" ::: "memory");
}
template <int N>
__device__ __forceinline__ void cp_wait() {
    asm volatile("cp.async.wait_group %0;\n" :: "n"(N) : "memory");
}

// ---------------- 2-stage pipelined split-bf16 HMMA GEMM (BM=128, MAXCTA CTAs/SM) ----------------
template <int K, int NCOLS, bool BIAS, bool SPLIT_EPI, bool DUAL, bool ROW_SCALE, int MAXCTA>
__global__ __launch_bounds__(256, MAXCTA)
void mm_kernel(const __nv_bfloat16* __restrict__ Ah, const __nv_bfloat16* __restrict__ Al,
               const __nv_bfloat16* __restrict__ Bh, const __nv_bfloat16* __restrict__ Bl,
               const float* __restrict__ bias, float* __restrict__ C,
               __nv_bfloat16* __restrict__ Chi, __nv_bfloat16* __restrict__ Clo,
               float* __restrict__ C2, int M) {
    constexpr int BM = 128;
    constexpr int BN = (NCOLS < 128) ? NCOLS : 128;
    constexpr int BK = 32;
    constexpr int SA = BK + 8;
    constexpr int WM = (BN == 64) ? 32 : 64;
    constexpr int WN = 32;
    constexpr int WGN = BN / WN;
    constexpr int MFR = WM / 16;
    constexpr int NFR = WN / 8;
    constexpr int NT = K / BK;
    constexpr int STG = 2 * (BM + BN) * SA;

    extern __shared__ __nv_bfloat16 smem[];
    const uint32_t sbase = (uint32_t)__cvta_generic_to_shared(smem);

    const int tid = threadIdx.x, wid = tid >> 5, lane = tid & 31;
    const int warp_m = wid / WGN, warp_n = wid % WGN;
    const int rowBase = blockIdx.x * BM;
    const int colBase = blockIdx.y * BN;
    const int gID = lane >> 2, tig = lane & 3;

    float acc[MFR][NFR][4] = {};

    auto load_stage = [&](int k0, int st) {
        const int aoff = st * STG;
#pragma unroll
        for (int i = tid; i < BM * 4; i += 256) {
            int r = i >> 2, q = i & 3;
            int gr = rowBase + r;
            bool ok = gr < M;
            size_t go = (size_t)(ok ? gr : 0) * K + k0 + q * 8;
            uint32_t sa = sbase + (uint32_t)(aoff + r * SA + q * 8) * 2;
            cp16(sa, Ah + go, ok);
            cp16(sa + (uint32_t)(BM * SA) * 2, Al + go, ok);
        }
        const int boff = st * STG + 2 * BM * SA;
#pragma unroll
        for (int i = tid; i < BN * 4; i += 256) {
            int r = i >> 2, q = i & 3;
            size_t go = (size_t)(colBase + r) * K + k0 + q * 8;
            uint32_t sa = sbase + (uint32_t)(boff + r * SA + q * 8) * 2;
            cp16(sa, Bh + go, true);
            cp16(sa + (uint32_t)(BN * SA) * 2, Bl + go, true);
        }
        cp_commit();
    };

    load_stage(0, 0);
    if (NT > 1) load_stage(BK, 1);

    for (int kt = 0; kt < NT; kt++) {
        if (kt + 1 < NT) cp_wait<1>(); else cp_wait<0>();
        __syncthreads();

        const int st = kt & 1;
        const uint32_t ah_base = sbase + (uint32_t)(st * STG) * 2;
        const uint32_t al_base = ah_base + (uint32_t)(BM * SA) * 2;
        const uint32_t bh_base = ah_base + (uint32_t)(2 * BM * SA) * 2;
        const uint32_t bl_base = bh_base + (uint32_t)(BN * SA) * 2;

#pragma unroll
        for (int kk = 0; kk < BK; kk += 16) {
            uint32_t bfh[NFR][2], bfl[NFR][2];
            int bn = warp_n * WN + ((lane >> 4) << 3) + (lane & 7);
            int bk = kk + ((lane >> 3) & 1) * 8;
#pragma unroll
            for (int pr = 0; pr < NFR / 2; pr++) {
                uint32_t off = (uint32_t)((bn + pr * 16) * SA + bk) * 2;
                uint32_t rh[4], rl[4];
                ldsm4(rh, bh_base + off);
                ldsm4(rl, bl_base + off);
                bfh[pr * 2][0] = rh[0]; bfh[pr * 2][1] = rh[1];
                bfh[pr * 2 + 1][0] = rh[2]; bfh[pr * 2 + 1][1] = rh[3];
                bfl[pr * 2][0] = rl[0]; bfl[pr * 2][1] = rl[1];
                bfl[pr * 2 + 1][0] = rl[2]; bfl[pr * 2 + 1][1] = rl[3];
            }
            int arow = warp_m * WM + (lane & 15);
            int acol = kk + ((lane >> 4) << 3);
#pragma unroll
            for (int mf = 0; mf < MFR; mf++) {
                uint32_t afh[4], afl[4];
                uint32_t off = (uint32_t)((arow + mf * 16) * SA + acol) * 2;
                ldsm4(afh, ah_base + off);
                ldsm4(afl, al_base + off);
#pragma unroll
                for (int nf = 0; nf < NFR; nf++) {
                    mma_bf16(acc[mf][nf], afh, bfh[nf]);
                    mma_bf16(acc[mf][nf], afh, bfl[nf]);
                    mma_bf16(acc[mf][nf], afl, bfh[nf]);
                }
            }
        }
        if (kt + 2 < NT) {
            __syncthreads();
            load_stage((kt + 2) * BK, st);
        }
    }

    // ---- epilogue ----
#pragma unroll
    for (int mf = 0; mf < MFR; mf++) {
        int r0 = rowBase + warp_m * WM + mf * 16 + gID;
        float d0 = 1.f, d1 = 1.f;
        if (ROW_SCALE) {
            d0 = (r0 < M) ? g_dis[r0] : 0.f;
            d1 = (r0 + 8 < M) ? g_dis[r0 + 8] : 0.f;
        }
#pragma unroll
        for (int nf = 0; nf < NFR; nf++) {
            int col = colBase + warp_n * WN + nf * 8 + tig * 2;
            float v0 = acc[mf][nf][0], v1 = acc[mf][nf][1];
            float v2 = acc[mf][nf][2], v3 = acc[mf][nf][3];
            if (DUAL) {
                if (col < 64) {
                    if (r0 < M)
                        *reinterpret_cast<float2*>(C + (size_t)r0 * 64 + col) = make_float2(v0, v1);
                    if (r0 + 8 < M)
                        *reinterpret_cast<float2*>(C + (size_t)(r0 + 8) * 64 + col) = make_float2(v2, v3);
                } else {
                    int c2 = col - 64;
                    float bb0 = bias[c2], bb1 = bias[c2 + 1];
                    v0 += bb0; v1 += bb1; v2 += bb0; v3 += bb1;
                    if (r0 < M)
                        *reinterpret_cast<float2*>(C2 + (size_t)r0 * 64 + c2) = make_float2(v0, v1);
                    if (r0 + 8 < M)
                        *reinterpret_cast<float2*>(C2 + (size_t)(r0 + 8) * 64 + c2) = make_float2(v2, v3);
                }
                continue;
            }
            if (BIAS) {
                float bb0 = bias[col], bb1 = bias[col + 1];
                v0 += bb0; v1 += bb1; v2 += bb0; v3 += bb1;
            }
            if (ROW_SCALE) { v0 *= d0; v1 *= d0; v2 *= d1; v3 *= d1; }
            if (SPLIT_EPI) {
                v0 = lrelu(v0); v1 = lrelu(v1); v2 = lrelu(v2); v3 = lrelu(v3);
                if (r0 < M) {
                    __nv_bfloat16 h0 = __float2bfloat16_rn(v0);
                    __nv_bfloat16 h1 = __float2bfloat16_rn(v1);
                    __nv_bfloat162 ph, pl;
                    ph.x = h0; ph.y = h1;
                    pl.x = __float2bfloat16_rn(v0 - __bfloat162float(h0));
                    pl.y = __float2bfloat16_rn(v1 - __bfloat162float(h1));
                    *reinterpret_cast<__nv_bfloat162*>(Chi + (size_t)r0 * NCOLS + col) = ph;
                    *reinterpret_cast<__nv_bfloat162*>(Clo + (size_t)r0 * NCOLS + col) = pl;
                }
                if (r0 + 8 < M) {
                    __nv_bfloat16 h2 = __float2bfloat16_rn(v2);
                    __nv_bfloat16 h3 = __float2bfloat16_rn(v3);
                    __nv_bfloat162 ph, pl;
                    ph.x = h2; ph.y = h3;
                    pl.x = __float2bfloat16_rn(v2 - __bfloat162float(h2));
                    pl.y = __float2bfloat16_rn(v3 - __bfloat162float(h3));
                    *reinterpret_cast<__nv_bfloat162*>(Chi + (size_t)(r0 + 8) * NCOLS + col) = ph;
                    *reinterpret_cast<__nv_bfloat162*>(Clo + (size_t)(r0 + 8) * NCOLS + col) = pl;
                }
            } else {
                if (r0 < M)
                    *reinterpret_cast<float2*>(C + (size_t)r0 * NCOLS + col) = make_float2(v0, v1);
                if (r0 + 8 < M)
                    *reinterpret_cast<float2*>(C + (size_t)(r0 + 8) * NCOLS + col) = make_float2(v2, v3);
            }
        }
    }
}

// ---------------- CSR gather aggregation ----------------
template <int F, bool LEAKY, bool BIAS, bool SPLIT, bool PRESCALED, bool OUTSCALE>
__global__ __launch_bounds__(256)
void agg_kernel(const float* __restrict__ in, float* __restrict__ out,
                const float* __restrict__ bias,
                __nv_bfloat16* __restrict__ oh, __nv_bfloat16* __restrict__ ol) {
    int warp = (blockIdx.x * 256 + threadIdx.x) >> 5;
    int lane = threadIdx.x & 31;
    if (warp >= NN) return;
    const int n = warp;
    const float dn = g_dis[n];
    constexpr int R = F / 32;
    float acc[R];
    const float wself = PRESCALED ? 1.f : dn * dn;
#pragma unroll
    for (int r = 0; r < R; r++) {
        float v = in[(size_t)n * F + lane + r * 32];
        if (LEAKY) v = lrelu(v);
        acc[r] = v * wself;
    }
    const int e0 = g_rowptr[n], e1 = g_rowptr[n + 1];
    int e = e0;
    for (; e + 3 < e1; e += 4) {
        int s0 = g_col[e], s1 = g_col[e + 1], s2 = g_col[e + 2], s3 = g_col[e + 3];
        float w0 = 1.f, w1 = 1.f, w2 = 1.f, w3 = 1.f;
        if (!PRESCALED) {
            w0 = g_dis[s0] * dn; w1 = g_dis[s1] * dn;
            w2 = g_dis[s2] * dn; w3 = g_dis[s3] * dn;
        }
#pragma unroll
        for (int r = 0; r < R; r++) {
            float va = in[(size_t)s0 * F + lane + r * 32];
            float vb = in[(size_t)s1 * F + lane + r * 32];
            float vc = in[(size_t)s2 * F + lane + r * 32];
            float vd = in[(size_t)s3 * F + lane + r * 32];
            if (LEAKY) { va = lrelu(va); vb = lrelu(vb); vc = lrelu(vc); vd = lrelu(vd); }
            if (PRESCALED) acc[r] += (va + vb) + (vc + vd);
            else acc[r] += va * w0 + vb * w1 + vc * w2 + vd * w3;
        }
    }
    for (; e < e1; e++) {
        int s0 = g_col[e];
        float w0 = PRESCALED ? 1.f : g_dis[s0] * dn;
#pragma unroll
        for (int r = 0; r < R; r++) {
            float va = in[(size_t)s0 * F + lane + r * 32];
            if (LEAKY) va = lrelu(va);
            acc[r] += PRESCALED ? va : va * w0;
        }
    }
#pragma unroll
    for (int r = 0; r < R; r++) {
        float o = acc[r];
        if (BIAS) o += bias[lane + r * 32];
        if (PRESCALED || OUTSCALE) o *= dn;
        if (SPLIT) {
            __nv_bfloat16 h = __float2bfloat16_rn(o);
            oh[(size_t)n * F + lane + r * 32] = h;
            ol[(size_t)n * F + lane + r * 32] = __float2bfloat16_rn(o - __bfloat162float(h));
        } else {
            out[(size_t)n * F + lane + r * 32] = o;
        }
    }
}

// ---------------- fused L4 agg (prescaled input) + bias + leaky + residual + layernorm ----------------
__global__ __launch_bounds__(256)
void agg_ln_kernel(const float* __restrict__ q4, const float* __restrict__ b4,
                   const float* __restrict__ resid,
                   const float* __restrict__ gamma, const float* __restrict__ beta,
                   float* __restrict__ z) {
    int warp = (blockIdx.x * 256 + threadIdx.x) >> 5;
    int lane = threadIdx.x & 31;
    if (warp >= NN) return;
    const int n = warp;
    const float dn = g_dis[n];
    float a0 = q4[(size_t)n * 64 + lane];
    float a1 = q4[(size_t)n * 64 + lane + 32];
    const int e0 = g_rowptr[n], e1 = g_rowptr[n + 1];
    int e = e0;
    for (; e + 3 < e1; e += 4) {
        int s0 = g_col[e], s1 = g_col[e + 1], s2 = g_col[e + 2], s3 = g_col[e + 3];
        a0 += (q4[(size_t)s0 * 64 + lane] + q4[(size_t)s1 * 64 + lane])
            + (q4[(size_t)s2 * 64 + lane] + q4[(size_t)s3 * 64 + lane]);
        a1 += (q4[(size_t)s0 * 64 + lane + 32] + q4[(size_t)s1 * 64 + lane + 32])
            + (q4[(size_t)s2 * 64 + lane + 32] + q4[(size_t)s3 * 64 + lane + 32]);
    }
    for (; e < e1; e++) {
        int s0 = g_col[e];
        a0 += q4[(size_t)s0 * 64 + lane];
        a1 += q4[(size_t)s0 * 64 + lane + 32];
    }
    float v0 = lrelu(a0 * dn + b4[lane]) + resid[(size_t)n * 64 + lane];
    float v1 = lrelu(a1 * dn + b4[lane + 32]) + resid[(size_t)n * 64 + lane + 32];
    float s = v0 + v1, sq = v0 * v0 + v1 * v1;
#pragma unroll
    for (int off = 16; off; off >>= 1) {
        s += __shfl_xor_sync(0xFFFFFFFFu, s, off);
        sq += __shfl_xor_sync(0xFFFFFFFFu, sq, off);
    }
    float mean = s * (1.f / 64.f);
    float var = sq * (1.f / 64.f) - mean * mean;
    float inv = rsqrtf(var + 1e-5f);
    z[(size_t)n * 64 + lane]      = (v0 - mean) * inv * gamma[lane]      + beta[lane];
    z[(size_t)n * 64 + lane + 32] = (v1 - mean) * inv * gamma[lane + 32] + beta[lane + 32];
}

// ---------------- pool stage 1 ----------------
__global__ void pool1_kernel(const float* __restrict__ z) {
    int g = blockIdx.x, part = blockIdx.y, j = threadIdx.x;
    int s = (g * NN + GG - 1) / GG;
    int e = ((g + 1) * NN + GG - 1) / GG;
    int cnt = e - s;
    int ps = s + (cnt * part) / 16;
    int pe = s + (cnt * (part + 1)) / 16;
    float m = -3.402823e38f;
    for (int n = ps; n < pe; n++) m = fmaxf(m, z[(size_t)n * 64 + j]);
    g_pp[(g * 16 + part) * 64 + j] = m;
}

// ---------------- fused pool stage 2 + head ----------------
__global__ void head_kernel(const float* __restrict__ fc1W, const float* __restrict__ fc1b,
                            const float* __restrict__ fng, const float* __restrict__ fnb,
                            const float* __restrict__ fc2W, const float* __restrict__ fc2b,
                            float* __restrict__ out) {
    __shared__ float ps[64];
    __shared__ float q[64];
    __shared__ float red[64];
    int g = blockIdx.x, j = threadIdx.x;
    float m = -3.402823e38f;
#pragma unroll
    for (int part = 0; part < 16; part++)
        m = fmaxf(m, g_pp[(g * 16 + part) * 64 + j]);
    ps[j] = m;
    __syncthreads();
    float acc = fc1b[j];
#pragma unroll 8
    for (int k = 0; k < 64; k++) acc += ps[k] * fc1W[k * 64 + j];
    red[j] = acc;
    __syncthreads();
#pragma unroll
    for (int off = 32; off; off >>= 1) { if (j < off) red[j] += red[j + off]; __syncthreads(); }
    float mean = red[0] * (1.f / 64.f);
    __syncthreads();
    float d = acc - mean;
    red[j] = d * d;
    __syncthreads();
#pragma unroll
    for (int off = 32; off; off >>= 1) { if (j < off) red[j] += red[j + off]; __syncthreads(); }
    float var = red[0] * (1.f / 64.f);
    float qn = d * rsqrtf(var + 1e-5f) * fng[j] + fnb[j];
    q[j] = lrelu(qn);
    __syncthreads();
    if (j < 16) {
        float o = fc2b[j];
#pragma unroll 8
        for (int k = 0; k < 64; k++) o += q[k] * fc2W[k * 16 + j];
        out[g * 16 + j] = o;
    }
}

// ---------------- launcher ----------------
static inline int mm_smem_bytes(int bn) { return 2 * 2 * (128 + bn) * 40 * 2; }

extern "C" void kernel_launch(void* const* d_in, const int* in_sizes, int n_in,
                              void* d_out, int out_size) {
    (void)in_sizes; (void)n_in; (void)out_size;
    const float* x   = (const float*)d_in[0];
    const int*   ei  = (const int*)d_in[1];
    const float *W1 = (const float*)d_in[3],  *b1 = (const float*)d_in[4];
    const float *W2 = (const float*)d_in[5],  *b2 = (const float*)d_in[6];
    const float *W3 = (const float*)d_in[7],  *b3 = (const float*)d_in[8];
    const float *W4 = (const float*)d_in[9],  *b4 = (const float*)d_in[10];
    const float *Wr = (const float*)d_in[11], *br = (const float*)d_in[12];
    const float *lng = (const float*)d_in[13], *lnb = (const float*)d_in[14];
    const float *fc1W = (const float*)d_in[15], *fc1b = (const float*)d_in[16];
    const float *fng = (const float*)d_in[17], *fnb = (const float*)d_in[18];
    const float *fc2W = (const float*)d_in[19], *fc2b = (const float*)d_in[20];
    float* out = (float*)d_out;

    float *bufA, *bufB, *resid;
    __nv_bfloat16 *ah, *al, *bh, *bl, *xh, *xl, *wh, *wl;
    cudaGetSymbolAddress((void**)&bufA, g_bufA);
    cudaGetSymbolAddress((void**)&bufB, g_bufB);
    cudaGetSymbolAddress((void**)&resid, g_resid);
    cudaGetSymbolAddress((void**)&ah, g_ah);
    cudaGetSymbolAddress((void**)&al, g_al);
    cudaGetSymbolAddress((void**)&bh, g_bh);
    cudaGetSymbolAddress((void**)&bl, g_bl);
    cudaGetSymbolAddress((void**)&xh, g_xh);
    cudaGetSymbolAddress((void**)&xl, g_xl);
    cudaGetSymbolAddress((void**)&wh, g_wh);
    cudaGetSymbolAddress((void**)&wl, g_wl);

    __nv_bfloat16 *w1h = wh + 0,      *w1l = wl + 0;
    __nv_bfloat16 *w2h = wh + 16384,  *w2l = wl + 16384;
    __nv_bfloat16 *w3h = wh + 32768,  *w3l = wl + 32768;
    __nv_bfloat16 *w4h = wh + 163840, *w4l = wl + 163840;

    const int* src = ei;
    const int* dst = ei + EE;

    cudaFuncSetAttribute(mm_kernel<128, 128, false, false, true, false, 2>, cudaFuncAttributeMaxDynamicSharedMemorySize, mm_smem_bytes(128));
    cudaFuncSetAttribute(mm_kernel<64, 256, true, false, false, true, 2>,   cudaFuncAttributeMaxDynamicSharedMemorySize, mm_smem_bytes(128));
    cudaFuncSetAttribute(mm_kernel<256, 512, true, true, false, false, 2>,  cudaFuncAttributeMaxDynamicSharedMemorySize, mm_smem_bytes(128));
    cudaFuncSetAttribute(mm_kernel<512, 64, false, false, false, true, 3>,  cudaFuncAttributeMaxDynamicSharedMemorySize, mm_smem_bytes(64));

    // side stream + events (host objects, created once)
    static cudaStream_t s2 = nullptr;
    static cudaEvent_t evFork = nullptr, evJoin = nullptr, evW = nullptr;
    if (s2 == nullptr) {
        cudaStreamCreateWithFlags(&s2, cudaStreamNonBlocking);
        cudaEventCreateWithFlags(&evFork, cudaEventDisableTiming);
        cudaEventCreateWithFlags(&evJoin, cudaEventDisableTiming);
        cudaEventCreateWithFlags(&evW, cudaEventDisableTiming);
    }

    const int MT = (NN + 127) / 128;
    const int AGG_BLOCKS = (NN + 7) / 8;

    // ---- fork ----
    cudaEventRecord(evFork, 0);
    cudaStreamWaitEvent(s2, evFork, 0);

    // s2 branch: weight split first (gates mm_L1), then CSR chain
    wsplit_all_kernel<<<(196608 + 255) / 256, 256, 0, s2>>>(W1, Wr, W2, W3, W4, wh, wl);
    cudaEventRecord(evW, s2);
    zero_kernel<<<(NN + 255) / 256, 256, 0, s2>>>();
    count_deg_kernel<<<(EE + 255) / 256, 256, 0, s2>>>(dst);
    bsum_kernel<<<NB, 1024, 0, s2>>>();
    rowptr_kernel<<<NB, 1024, 0, s2>>>();
    fill_kernel<<<(EE + 255) / 256, 256, 0, s2>>>(src, dst);
    cudaEventRecord(evJoin, s2);

    // legacy branch: x split, then (after weights ready) L1 GEMM
    split_kernel<<<(NN * 32 + 255) / 256, 256>>>(
        reinterpret_cast<const float4*>(x), reinterpret_cast<uint2*>(xh),
        reinterpret_cast<uint2*>(xl), NN * 32);
    cudaStreamWaitEvent(0, evW, 0);
    mm_kernel<128, 128, false, false, true, false, 2><<<dim3(MT, 1), 256, mm_smem_bytes(128)>>>(
        xh, xl, w1h, w1l, br, bufA, nullptr, nullptr, resid, NN);

    // ---- join ----
    cudaStreamWaitEvent(0, evJoin, 0);

    // agg1: q1 = dis[n]*(agg(t1)+b1)
    agg_kernel<64, false, true, false, false, true><<<AGG_BLOCKS, 256>>>(bufA, bufB, b1, nullptr, nullptr);
    // agg2 (prescaled): g2 -> split
    agg_kernel<64, true, false, true, true, false><<<AGG_BLOCKS, 256>>>(bufB, nullptr, nullptr, ah, al);
    // L2 GEMM with ROW_SCALE
    mm_kernel<64, 256, true, false, false, true, 2><<<dim3(MT, 2), 256, mm_smem_bytes(128)>>>(
        ah, al, w2h, w2l, b2, bufB, nullptr, nullptr, nullptr, NN);
    // agg3 (prescaled): g3 -> split
    agg_kernel<256, true, false, true, true, false><<<AGG_BLOCKS, 256>>>(bufB, nullptr, nullptr, ah, al);
    // L3 GEMM (split epilogue)
    mm_kernel<256, 512, true, true, false, false, 2><<<dim3(MT, 4), 256, mm_smem_bytes(128)>>>(
        ah, al, w3h, w3l, b3, nullptr, bh, bl, nullptr, NN);
    // L4 GEMM with ROW_SCALE (3 CTAs/SM)
    mm_kernel<512, 64, false, false, false, true, 3><<<dim3(MT, 1), 256, mm_smem_bytes(64)>>>(
        bh, bl, w4h, w4l, nullptr, bufA, nullptr, nullptr, nullptr, NN);
    // fused agg (prescaled) + bias + leaky + residual + LN
    agg_ln_kernel<<<AGG_BLOCKS, 256>>>(bufA, b4, resid, lng, lnb, bufB);
    // pool + fused head
    pool1_kernel<<<dim3(GG, 16), 64>>>(bufB);
    head_kernel<<<GG, 64>>>(fc1W, fc1b, fng, fnb, fc2W, fc2b, out);
}